// round 6
// baseline (speedup 1.0000x reference)
#include <cuda_runtime.h>
#include <cuda_bf16.h>
#include <stdint.h>

#define S_LEN 4096
#define D_MODEL 2048
#define D_CQ 1536
#define H 8
#define D 128
#define NEG (-1000000000.0f)
#define HAD_SCALE 0.08838834764831845f   // 128^-0.5

// ---------------- scratch (device globals; no allocation allowed) ----------
__device__ __nv_bfloat16 g_qprime[S_LEN * H * D];     // [t][h][d]
__device__ __nv_bfloat16 g_kprime[S_LEN * D];         // [s][d]
__device__ float         g_w[S_LEN * H];              // [t][h]
__device__ __nv_bfloat16 g_xb [S_LEN * D_MODEL];      // x bf16
__device__ __nv_bfloat16 g_qlb[S_LEN * D_CQ];         // q_latent bf16
__device__ __nv_bfloat16 g_wqt[(H * D) * D_CQ];       // Wq^T  [N=1024][K=1536]
__device__ __nv_bfloat16 g_wkt[D * D_MODEL];          // Wk^T  [N=128][K=2048]

// ---------------- asm helpers ---------------------------------------------
__device__ __forceinline__ uint32_t smem_u32(const void* p) {
    return (uint32_t)__cvta_generic_to_shared(p);
}
__device__ __forceinline__ void cp16(uint32_t dst, const void* src) {
    asm volatile("cp.async.cg.shared.global [%0], [%1], 16;\n" :: "r"(dst), "l"(src));
}
__device__ __forceinline__ void cp_commit() {
    asm volatile("cp.async.commit_group;\n" ::: "memory");
}
template<int N> __device__ __forceinline__ void cp_wait() {
    asm volatile("cp.async.wait_group %0;\n" :: "n"(N) : "memory");
}
__device__ __forceinline__ void ldmx4(uint32_t* r, uint32_t a) {
    asm volatile("ldmatrix.sync.aligned.m8n8.x4.shared.b16 {%0,%1,%2,%3}, [%4];\n"
                 : "=r"(r[0]), "=r"(r[1]), "=r"(r[2]), "=r"(r[3]) : "r"(a));
}
__device__ __forceinline__ void mma16816(float c[4], const uint32_t a[4], const uint32_t b[2]) {
    asm volatile(
        "mma.sync.aligned.m16n8k16.row.col.f32.bf16.bf16.f32 "
        "{%0,%1,%2,%3}, {%4,%5,%6,%7}, {%8,%9}, {%0,%1,%2,%3};\n"
        : "+f"(c[0]), "+f"(c[1]), "+f"(c[2]), "+f"(c[3])
        : "r"(a[0]), "r"(a[1]), "r"(a[2]), "r"(a[3]), "r"(b[0]), "r"(b[1]));
}

// ---------------- fp32 -> bf16 convert (x + q_latent, one launch) ----------
#define N_X  (S_LEN * D_MODEL)            // 8388608
#define N_QL (S_LEN * D_CQ)               // 6291456
#define CVT_BLOCKS ((N_X + N_QL) / 1024)

__global__ __launch_bounds__(256) void cvt_all_kernel(const float* __restrict__ x,
                                                      const float* __restrict__ ql) {
    long i = (long)(blockIdx.x * 256 + threadIdx.x) * 4;
    const float* s;
    __nv_bfloat16* d;
    long base;
    if (i < N_X) { s = x;  d = g_xb;  base = 0; }
    else         { s = ql; d = g_qlb; base = N_X; }
    long j = i - base;
    float4 v = *(const float4*)(s + j);
    __nv_bfloat162 p0 = __floats2bfloat162_rn(v.x, v.y);
    __nv_bfloat162 p1 = __floats2bfloat162_rn(v.z, v.w);
    uint2 u;
    u.x = *(uint32_t*)&p0;
    u.y = *(uint32_t*)&p1;
    *(uint2*)(d + j) = u;
}

// ---------------- transpose-convert: src[K][N] f32 -> dst[N][K] bf16 -------
__global__ __launch_bounds__(256) void tconv_kernel(const float* __restrict__ src,
                                                    __nv_bfloat16* __restrict__ dst,
                                                    int K, int N) {
    __shared__ float t[32][33];
    const int k0 = blockIdx.x * 32, n0 = blockIdx.y * 32;
    const int tx = threadIdx.x & 31, ty = threadIdx.x >> 5;  // 32 x 8
    #pragma unroll
    for (int i = 0; i < 4; i++)
        t[ty + 8 * i][tx] = src[(size_t)(k0 + ty + 8 * i) * N + n0 + tx];
    __syncthreads();
    #pragma unroll
    for (int i = 0; i < 4; i++)
        dst[(size_t)(n0 + ty + 8 * i) * K + k0 + tx] = __float2bfloat16(t[tx][ty + 8 * i]);
}

// ---------------------------------------------------------------------------
// Merged projection GEMM (mma.sync, scores-style mainloop).
// grid (9, 32): blockIdx.x 0..7 -> Q head tiles, 8 -> K tile (+LayerNorm).
// 512 threads, 128x128 tile, warp tile 32x32, K chunks of 128,
// double-buffered A and B (each [128][272B], K-major, pad 8 bf16).
// dyn smem: 4 * 34816 = 139264 B; epilogue Es[128][132] f32 aliases it.
// ---------------------------------------------------------------------------
__global__ __launch_bounds__(512) void proj_kernel(const float* __restrict__ ln_g,
                                                   const float* __restrict__ ln_b) {
    extern __shared__ char sm[];
    __shared__ float s_mu[128], s_rs[128];

    const int tile = blockIdx.x;
    const bool isK = (tile == 8);
    const __nv_bfloat16* A  = isK ? g_xb  : g_qlb;   // [4096][Kdim]
    const __nv_bfloat16* Bt = isK ? g_wkt : g_wqt;   // [N][Kdim]
    const int Kdim = isK ? D_MODEL : D_CQ;
    const int n0   = isK ? 0 : tile * 128;
    __nv_bfloat16* outp = isK ? g_kprime : g_qprime;
    const int Old  = isK ? D : (H * D);
    const int m0 = blockIdx.y * 128;

    const int tid = threadIdx.x, lane = tid & 31, warp = tid >> 5;
    const int wm = (warp & 3) * 32;          // 4 m-warps
    const int wn = (warp >> 2) * 32;         // 4 n-warps
    const int gid = lane >> 2, tig = lane & 3;

    const int KT = Kdim >> 7;                // chunks of 128

    auto fill = [&](int buf, int k0) {
        char* as = sm + buf * 34816;
        char* bs = sm + 69632 + buf * 34816;
        #pragma unroll
        for (int i = 0; i < 4; i++) {
            int c = tid + i * 512;
            int r = c >> 4, g = c & 15;
            cp16(smem_u32(as + r * 272 + g * 16), A  + (size_t)(m0 + r) * Kdim + k0 + g * 8);
        }
        #pragma unroll
        for (int i = 0; i < 4; i++) {
            int c = tid + i * 512;
            int r = c >> 4, g = c & 15;
            cp16(smem_u32(bs + r * 272 + g * 16), Bt + (size_t)(n0 + r) * Kdim + k0 + g * 8);
        }
    };

    float acc[2][4][4];
    #pragma unroll
    for (int mt = 0; mt < 2; mt++)
        #pragma unroll
        for (int nt = 0; nt < 4; nt++)
            #pragma unroll
            for (int j = 0; j < 4; j++) acc[mt][nt][j] = 0.f;

    fill(0, 0);
    cp_commit();

    for (int kt = 0; kt < KT; kt++) {
        cp_wait<0>();
        __syncthreads();
        if (kt + 1 < KT) {
            fill((kt + 1) & 1, (kt + 1) * 128);
            cp_commit();
        }
        const char* as = sm + (kt & 1) * 34816;
        const char* bs = sm + 69632 + (kt & 1) * 34816;
        #pragma unroll
        for (int kc = 0; kc < 128; kc += 16) {
            uint32_t af[2][4];
            #pragma unroll
            for (int mt = 0; mt < 2; mt++) {
                uint32_t ad = smem_u32(as + (wm + mt * 16 + (lane & 15)) * 272
                                          + (kc + 8 * (lane >> 4)) * 2);
                ldmx4(af[mt], ad);
            }
            #pragma unroll
            for (int ng = 0; ng < 2; ng++) {
                uint32_t bf[4];
                int row = wn + ng * 16 + ((lane >> 4) << 3) + (lane & 7);
                int ck  = kc + 8 * ((lane >> 3) & 1);
                ldmx4(bf, smem_u32(bs + row * 272 + ck * 2));
                #pragma unroll
                for (int mt = 0; mt < 2; mt++) {
                    mma16816(acc[mt][2 * ng],     af[mt], bf + 0);
                    mma16816(acc[mt][2 * ng + 1], af[mt], bf + 2);
                }
            }
        }
        __syncthreads();   // all warps done with this buffer before it is refilled
    }

    // ---- epilogue: acc -> Es (fp32, aliases stage buffers) ----
    float* Es = (float*)sm;    // [128][132]
    #pragma unroll
    for (int mt = 0; mt < 2; mt++) {
        int r0 = wm + mt * 16 + gid;
        int r1 = r0 + 8;
        #pragma unroll
        for (int nt = 0; nt < 4; nt++) {
            int c = wn + nt * 8 + 2 * tig;
            Es[r0 * 132 + c]     = acc[mt][nt][0];
            Es[r0 * 132 + c + 1] = acc[mt][nt][1];
            Es[r1 * 132 + c]     = acc[mt][nt][2];
            Es[r1 * 132 + c + 1] = acc[mt][nt][3];
        }
    }
    __syncthreads();

    if (isK) {
        if (tid < 128) {
            float sum = 0.f, sq = 0.f;
            #pragma unroll 4
            for (int d2 = 0; d2 < 128; d2++) {
                float v = Es[tid * 132 + d2];
                sum += v; sq += v * v;
            }
            float mu  = sum * (1.0f / 128.0f);
            float var = sq * (1.0f / 128.0f) - mu * mu;
            s_mu[tid] = mu;
            s_rs[tid] = rsqrtf(var + 1e-5f);
        }
        __syncthreads();
        for (int it = tid; it < 128 * 128; it += 512) {
            int r = it >> 7, d2 = it & 127;
            Es[r * 132 + d2] = (Es[r * 132 + d2] - s_mu[r]) * s_rs[r] * ln_g[d2] + ln_b[d2];
        }
        __syncthreads();
    }
    // RoPE: pairs (j, j+32), j<32; freq = 10000^(-j/32)
    for (int it = tid; it < 128 * 32; it += 512) {
        int r = it >> 5, j = it & 31;
        float t = (float)(m0 + r);
        float freq = exp2f((float)j * (-0.41524101186092029f));
        float sn, cs;
        sincosf(t * freq, &sn, &cs);
        float x1 = Es[r * 132 + j], x2 = Es[r * 132 + j + 32];
        Es[r * 132 + j]      = x1 * cs - x2 * sn;
        Es[r * 132 + j + 32] = x1 * sn + x2 * cs;
    }
    // Hadamard (7 butterfly stages)
    for (int step = 1; step < 128; step <<= 1) {
        __syncthreads();
        for (int it = tid; it < 128 * 64; it += 512) {
            int r = it >> 6, pp = it & 63;
            int i = ((pp & ~(step - 1)) << 1) | (pp & (step - 1));
            float a = Es[r * 132 + i], b = Es[r * 132 + i + step];
            Es[r * 132 + i]        = a + b;
            Es[r * 132 + i + step] = a - b;
        }
    }
    __syncthreads();
    for (int it = tid; it < 128 * 128; it += 512) {
        int r = it >> 7, d2 = it & 127;
        outp[(size_t)(m0 + r) * Old + n0 + d2] = __float2bfloat16(Es[r * 132 + d2] * HAD_SCALE);
    }
}

// ---------------------------------------------------------------------------
// w[t][h] = x[t] . Wwt[:,h]   (reads bf16 x copy; Wwt fp32)
// ---------------------------------------------------------------------------
__global__ __launch_bounds__(256) void w_kernel(const float* __restrict__ Wwt) {
    const int t = blockIdx.x;
    const int warp = threadIdx.x >> 5, lane = threadIdx.x & 31;
    float sum = 0.f;
    for (int k = lane; k < D_MODEL; k += 32)
        sum += __bfloat162float(g_xb[(size_t)t * D_MODEL + k]) * Wwt[(size_t)k * H + warp];
    #pragma unroll
    for (int o = 16; o > 0; o >>= 1) sum += __shfl_xor_sync(0xffffffffu, sum, o);
    if (lane == 0) g_w[(size_t)t * H + warp] = sum;
}

// ---------------------------------------------------------------------------
// scores: tile 128(t) x 128(s) per CTA, grid (32, 32), 512 threads.
// K-tile resident; per-head Q double-buffered via cp.async.
// dyn smem: Ks 128*272 + Qs 2*128*272 = 104448 B.
// ---------------------------------------------------------------------------
__global__ __launch_bounds__(512) void scores_kernel(float* __restrict__ out) {
    const int s0 = blockIdx.x * 128;
    const int t0 = blockIdx.y * 128;
    const int tid = threadIdx.x;

    if (s0 > t0 + 127) {   // fully masked tile
        const float4 n4 = make_float4(NEG, NEG, NEG, NEG);
        for (int it = tid; it < 128 * 32; it += 512) {
            int r = it >> 5, c = (it & 31) * 4;
            *(float4*)&out[(size_t)(t0 + r) * S_LEN + s0 + c] = n4;
        }
        return;
    }

    extern __shared__ char sm[];
    char* Ks = sm;                          // [128][136] bf16
    __shared__ float ws[128][8];

    const int lane = tid & 31, warp = tid >> 5;
    const int wm = (warp & 3) * 32;
    const int wn = (warp >> 2) * 32;
    const int gid = lane >> 2, tig = lane & 3;

    for (int it = tid; it < 1024; it += 512)
        ws[it >> 3][it & 7] = g_w[(size_t)(t0 + (it >> 3)) * H + (it & 7)];

    #pragma unroll
    for (int i = 0; i < 4; i++) {
        int c = tid + i * 512;
        int r = c >> 4, sg = c & 15;
        cp16(smem_u32(Ks + r * 272 + sg * 16), g_kprime + (size_t)(s0 + r) * D + sg * 8);
    }
    {
        char* Q0 = sm + 34816;
        #pragma unroll
        for (int i = 0; i < 4; i++) {
            int c = tid + i * 512;
            int r = c >> 4, sg = c & 15;
            cp16(smem_u32(Q0 + r * 272 + sg * 16),
                 g_qprime + ((size_t)(t0 + r) * H + 0) * D + sg * 8);
        }
    }
    cp_commit();

    float score[2][4][4];
    #pragma unroll
    for (int mt = 0; mt < 2; mt++)
        #pragma unroll
        for (int nt = 0; nt < 4; nt++)
            #pragma unroll
            for (int j = 0; j < 4; j++) score[mt][nt][j] = 0.f;

    for (int h = 0; h < H; h++) {
        cp_wait<0>();
        __syncthreads();
        if (h < 7) {
            char* Qn = sm + 34816 + ((h + 1) & 1) * 34816;
            #pragma unroll
            for (int i = 0; i < 4; i++) {
                int c = tid + i * 512;
                int r = c >> 4, sg = c & 15;
                cp16(smem_u32(Qn + r * 272 + sg * 16),
                     g_qprime + ((size_t)(t0 + r) * H + h + 1) * D + sg * 8);
            }
            cp_commit();
        }
        const char* Qb = sm + 34816 + (h & 1) * 34816;

        float acc[2][4][4];
        #pragma unroll
        for (int mt = 0; mt < 2; mt++)
            #pragma unroll
            for (int nt = 0; nt < 4; nt++)
                #pragma unroll
                for (int j = 0; j < 4; j++) acc[mt][nt][j] = 0.f;

        #pragma unroll
        for (int kc = 0; kc < 128; kc += 16) {
            uint32_t af[2][4];
            #pragma unroll
            for (int mt = 0; mt < 2; mt++) {
                uint32_t ad = smem_u32(Qb + (wm + mt * 16 + (lane & 15)) * 272
                                          + (kc + 8 * (lane >> 4)) * 2);
                ldmx4(af[mt], ad);
            }
            #pragma unroll
            for (int ng = 0; ng < 2; ng++) {
                uint32_t bf[4];
                int row = wn + ng * 16 + ((lane >> 4) << 3) + (lane & 7);
                int ck  = kc + 8 * ((lane >> 3) & 1);
                ldmx4(bf, smem_u32(Ks + row * 272 + ck * 2));
                #pragma unroll
                for (int mt = 0; mt < 2; mt++) {
                    mma16816(acc[mt][2 * ng],     af[mt], bf + 0);
                    mma16816(acc[mt][2 * ng + 1], af[mt], bf + 2);
                }
            }
        }
        #pragma unroll
        for (int mt = 0; mt < 2; mt++) {
            float w0 = ws[wm + mt * 16 + gid][h];
            float w1 = ws[wm + mt * 16 + 8 + gid][h];
            #pragma unroll
            for (int nt = 0; nt < 4; nt++) {
                score[mt][nt][0] += w0 * fmaxf(acc[mt][nt][0], 0.f);
                score[mt][nt][1] += w0 * fmaxf(acc[mt][nt][1], 0.f);
                score[mt][nt][2] += w1 * fmaxf(acc[mt][nt][2], 0.f);
                score[mt][nt][3] += w1 * fmaxf(acc[mt][nt][3], 0.f);
            }
        }
    }

    #pragma unroll
    for (int mt = 0; mt < 2; mt++) {
        int r0 = t0 + wm + mt * 16 + gid;
        int r1 = r0 + 8;
        #pragma unroll
        for (int nt = 0; nt < 4; nt++) {
            int cs = s0 + wn + nt * 8 + 2 * tig;
            out[(size_t)r0 * S_LEN + cs    ] = (cs     <= r0) ? score[mt][nt][0] * HAD_SCALE : NEG;
            out[(size_t)r0 * S_LEN + cs + 1] = (cs + 1 <= r0) ? score[mt][nt][1] * HAD_SCALE : NEG;
            out[(size_t)r1 * S_LEN + cs    ] = (cs     <= r1) ? score[mt][nt][2] * HAD_SCALE : NEG;
            out[(size_t)r1 * S_LEN + cs + 1] = (cs + 1 <= r1) ? score[mt][nt][3] * HAD_SCALE : NEG;
        }
    }
}

// ---------------------------------------------------------------------------
extern "C" void kernel_launch(void* const* d_in, const int* in_sizes, int n_in,
                              void* d_out, int out_size) {
    const float* x    = (const float*)d_in[0];
    const float* qlat = (const float*)d_in[1];
    const float* Wq   = (const float*)d_in[2];
    const float* Wk   = (const float*)d_in[3];
    const float* ln_g = (const float*)d_in[4];
    const float* ln_b = (const float*)d_in[5];
    const float* Wwt  = (const float*)d_in[6];
    float* out = (float*)d_out;

    void *wqt, *wkt;
    cudaGetSymbolAddress(&wqt, g_wqt);
    cudaGetSymbolAddress(&wkt, g_wkt);

    cudaFuncSetAttribute(proj_kernel,   cudaFuncAttributeMaxDynamicSharedMemorySize, 139264);
    cudaFuncSetAttribute(scores_kernel, cudaFuncAttributeMaxDynamicSharedMemorySize, 104448);

    cvt_all_kernel<<<CVT_BLOCKS, 256>>>(x, qlat);
    tconv_kernel<<<dim3(D_CQ / 32, (H * D) / 32), 256>>>(Wq, (__nv_bfloat16*)wqt, D_CQ, H * D);
    tconv_kernel<<<dim3(D_MODEL / 32, D / 32), 256>>>(Wk, (__nv_bfloat16*)wkt, D_MODEL, D);

    proj_kernel<<<dim3(9, S_LEN / 128), 512, 139264>>>(ln_g, ln_b);

    w_kernel<<<S_LEN, 256>>>(Wwt);

    scores_kernel<<<dim3(S_LEN / 128, S_LEN / 128), 512, 104448>>>(out);
}

// round 8
// speedup vs baseline: 1.2385x; 1.2385x over previous
#include <cuda_runtime.h>
#include <cuda_bf16.h>
#include <stdint.h>

#define S_LEN 4096
#define D_MODEL 2048
#define D_CQ 1536
#define H 8
#define D 128
#define NEG (-1000000000.0f)
#define HAD_SCALE 0.08838834764831845f   // 128^-0.5

// ---------------- scratch (device globals; no allocation allowed) ----------
__device__ __nv_bfloat16 g_qprime[S_LEN * H * D];     // [t][h][d]
__device__ __nv_bfloat16 g_kprime[S_LEN * D];         // [s][d]
__device__ float         g_w[S_LEN * H];              // [t][h]
__device__ __nv_bfloat16 g_xb [S_LEN * D_MODEL];      // x bf16
__device__ __nv_bfloat16 g_qlb[S_LEN * D_CQ];         // q_latent bf16
__device__ __nv_bfloat16 g_wqt[(H * D) * D_CQ];       // Wq^T  [N=1024][K=1536]
__device__ __nv_bfloat16 g_wkt[D * D_MODEL];          // Wk^T  [N=128][K=2048]
__device__ float         g_wwtT[H * D_MODEL];         // Wwt^T [h][k]

// ---------------- asm helpers ---------------------------------------------
__device__ __forceinline__ uint32_t smem_u32(const void* p) {
    return (uint32_t)__cvta_generic_to_shared(p);
}
__device__ __forceinline__ void cp16(uint32_t dst, const void* src) {
    asm volatile("cp.async.cg.shared.global [%0], [%1], 16;\n" :: "r"(dst), "l"(src));
}
__device__ __forceinline__ void cp_commit() {
    asm volatile("cp.async.commit_group;\n" ::: "memory");
}
template<int N> __device__ __forceinline__ void cp_wait() {
    asm volatile("cp.async.wait_group %0;\n" :: "n"(N) : "memory");
}
__device__ __forceinline__ void ldmx4(uint32_t* r, uint32_t a) {
    asm volatile("ldmatrix.sync.aligned.m8n8.x4.shared.b16 {%0,%1,%2,%3}, [%4];\n"
                 : "=r"(r[0]), "=r"(r[1]), "=r"(r[2]), "=r"(r[3]) : "r"(a));
}
__device__ __forceinline__ void mma16816(float c[4], const uint32_t a[4], const uint32_t b[2]) {
    asm volatile(
        "mma.sync.aligned.m16n8k16.row.col.f32.bf16.bf16.f32 "
        "{%0,%1,%2,%3}, {%4,%5,%6,%7}, {%8,%9}, {%0,%1,%2,%3};\n"
        : "+f"(c[0]), "+f"(c[1]), "+f"(c[2]), "+f"(c[3])
        : "r"(a[0]), "r"(a[1]), "r"(a[2]), "r"(a[3]), "r"(b[0]), "r"(b[1]));
}

// ---------------- fp32 -> bf16 convert (x + q_latent, one launch) ----------
#define N_X  (S_LEN * D_MODEL)            // 8388608
#define N_QL (S_LEN * D_CQ)               // 6291456
#define CVT_BLOCKS ((N_X + N_QL) / 1024)

__global__ __launch_bounds__(256) void cvt_all_kernel(const float* __restrict__ x,
                                                      const float* __restrict__ ql) {
    long i = (long)(blockIdx.x * 256 + threadIdx.x) * 4;
    const float* s;
    __nv_bfloat16* d;
    long base;
    if (i < N_X) { s = x;  d = g_xb;  base = 0; }
    else         { s = ql; d = g_qlb; base = N_X; }
    long j = i - base;
    float4 v = *(const float4*)(s + j);
    __nv_bfloat162 p0 = __floats2bfloat162_rn(v.x, v.y);
    __nv_bfloat162 p1 = __floats2bfloat162_rn(v.z, v.w);
    uint2 u;
    u.x = *(uint32_t*)&p0;
    u.y = *(uint32_t*)&p1;
    *(uint2*)(d + j) = u;
}

// ---------------- transpose-convert: src[K][N] f32 -> dst[N][K] bf16 -------
__global__ __launch_bounds__(256) void tconv_kernel(const float* __restrict__ src,
                                                    __nv_bfloat16* __restrict__ dst,
                                                    int K, int N) {
    __shared__ float t[32][33];
    const int k0 = blockIdx.x * 32, n0 = blockIdx.y * 32;
    const int tx = threadIdx.x & 31, ty = threadIdx.x >> 5;  // 32 x 8
    #pragma unroll
    for (int i = 0; i < 4; i++)
        t[ty + 8 * i][tx] = src[(size_t)(k0 + ty + 8 * i) * N + n0 + tx];
    __syncthreads();
    #pragma unroll
    for (int i = 0; i < 4; i++)
        dst[(size_t)(n0 + ty + 8 * i) * K + k0 + tx] = __float2bfloat16(t[tx][ty + 8 * i]);
}

// ---------------- transpose Wwt [K][8] f32 -> [8][K] f32 -------------------
__global__ __launch_bounds__(256) void wwt_t_kernel(const float* __restrict__ Wwt) {
    int k = blockIdx.x * 256 + threadIdx.x;
    #pragma unroll
    for (int h = 0; h < H; h++)
        g_wwtT[h * D_MODEL + k] = Wwt[(size_t)k * H + h];
}

// ---------------------------------------------------------------------------
// Merged projection GEMM (mma.sync, 3-stage cp.async ring, 1 sync/chunk).
// grid (9, 32): blockIdx.x 0..7 -> Q head tiles, 8 -> K tile (+LayerNorm).
// 512 threads, 128x128 tile, warp tile 32x32, K chunks of 128.
// dyn smem: 3 stages x (A 34816 + B 34816) = 208896 B; Es[128][132] aliases.
// ---------------------------------------------------------------------------
__global__ __launch_bounds__(512, 1) void proj_kernel(const float* __restrict__ ln_g,
                                                      const float* __restrict__ ln_b) {
    extern __shared__ char sm[];
    __shared__ float s_mu[128], s_rs[128];

    const int tile = blockIdx.x;
    const bool isK = (tile == 8);
    const __nv_bfloat16* A  = isK ? g_xb  : g_qlb;   // [4096][Kdim]
    const __nv_bfloat16* Bt = isK ? g_wkt : g_wqt;   // [N][Kdim]
    const int Kdim = isK ? D_MODEL : D_CQ;
    const int n0   = isK ? 0 : tile * 128;
    __nv_bfloat16* outp = isK ? g_kprime : g_qprime;
    const int Old  = isK ? D : (H * D);
    const int m0 = blockIdx.y * 128;

    const int tid = threadIdx.x, lane = tid & 31, warp = tid >> 5;
    const int wm = (warp & 3) * 32;          // 4 m-warps
    const int wn = (warp >> 2) * 32;         // 4 n-warps
    const int gid = lane >> 2, tig = lane & 3;

    const int KT = Kdim >> 7;                // chunks of 128

    auto fill = [&](int st, int k0) {
        char* as = sm + st * 69632;
        char* bs = as + 34816;
        #pragma unroll
        for (int i = 0; i < 4; i++) {
            int c = tid + i * 512;
            int r = c >> 4, g = c & 15;
            cp16(smem_u32(as + r * 272 + g * 16), A  + (size_t)(m0 + r) * Kdim + k0 + g * 8);
        }
        #pragma unroll
        for (int i = 0; i < 4; i++) {
            int c = tid + i * 512;
            int r = c >> 4, g = c & 15;
            cp16(smem_u32(bs + r * 272 + g * 16), Bt + (size_t)(n0 + r) * Kdim + k0 + g * 8);
        }
    };

    float acc[2][4][4];
    #pragma unroll
    for (int mt = 0; mt < 2; mt++)
        #pragma unroll
        for (int nt = 0; nt < 4; nt++)
            #pragma unroll
            for (int j = 0; j < 4; j++) acc[mt][nt][j] = 0.f;

    fill(0, 0);   cp_commit();
    fill(1, 128); cp_commit();

    int cs_ = 0;                   // compute slot = kt % 3
    for (int kt = 0; kt < KT; kt++) {
        cp_wait<1>();
        __syncthreads();           // slot (kt+2)%3 == (kt-1)%3 now free for refill
        if (kt + 2 < KT) {
            int fs = cs_ + 2; if (fs >= 3) fs -= 3;
            fill(fs, (kt + 2) * 128);
        }
        cp_commit();               // one group per iteration (possibly empty)

        const char* as = sm + cs_ * 69632;
        const char* bs = as + 34816;
        #pragma unroll
        for (int kc = 0; kc < 128; kc += 16) {
            uint32_t af[2][4];
            #pragma unroll
            for (int mt = 0; mt < 2; mt++) {
                uint32_t ad = smem_u32(as + (wm + mt * 16 + (lane & 15)) * 272
                                          + (kc + 8 * (lane >> 4)) * 2);
                ldmx4(af[mt], ad);
            }
            #pragma unroll
            for (int ng = 0; ng < 2; ng++) {
                uint32_t bf[4];
                int row = wn + ng * 16 + ((lane >> 4) << 3) + (lane & 7);
                int ck  = kc + 8 * ((lane >> 3) & 1);
                ldmx4(bf, smem_u32(bs + row * 272 + ck * 2));
                #pragma unroll
                for (int mt = 0; mt < 2; mt++) {
                    mma16816(acc[mt][2 * ng],     af[mt], bf + 0);
                    mma16816(acc[mt][2 * ng + 1], af[mt], bf + 2);
                }
            }
        }
        if (++cs_ == 3) cs_ = 0;
    }
    cp_wait<0>();
    __syncthreads();

    // ---- epilogue: acc -> Es (fp32, aliases stage buffers) ----
    float* Es = (float*)sm;    // [128][132]
    #pragma unroll
    for (int mt = 0; mt < 2; mt++) {
        int r0 = wm + mt * 16 + gid;
        int r1 = r0 + 8;
        #pragma unroll
        for (int nt = 0; nt < 4; nt++) {
            int c = wn + nt * 8 + 2 * tig;
            Es[r0 * 132 + c]     = acc[mt][nt][0];
            Es[r0 * 132 + c + 1] = acc[mt][nt][1];
            Es[r1 * 132 + c]     = acc[mt][nt][2];
            Es[r1 * 132 + c + 1] = acc[mt][nt][3];
        }
    }
    __syncthreads();

    if (isK) {
        if (tid < 128) {
            float sum = 0.f, sq = 0.f;
            #pragma unroll 4
            for (int d2 = 0; d2 < 128; d2++) {
                float v = Es[tid * 132 + d2];
                sum += v; sq += v * v;
            }
            float mu  = sum * (1.0f / 128.0f);
            float var = sq * (1.0f / 128.0f) - mu * mu;
            s_mu[tid] = mu;
            s_rs[tid] = rsqrtf(var + 1e-5f);
        }
        __syncthreads();
        for (int it = tid; it < 128 * 128; it += 512) {
            int r = it >> 7, d2 = it & 127;
            Es[r * 132 + d2] = (Es[r * 132 + d2] - s_mu[r]) * s_rs[r] * ln_g[d2] + ln_b[d2];
        }
        __syncthreads();
    }
    // RoPE: pairs (j, j+32), j<32; freq = 10000^(-j/32)
    for (int it = tid; it < 128 * 32; it += 512) {
        int r = it >> 5, j = it & 31;
        float t = (float)(m0 + r);
        float freq = exp2f((float)j * (-0.41524101186092029f));
        float sn, cs2;
        sincosf(t * freq, &sn, &cs2);
        float x1 = Es[r * 132 + j], x2 = Es[r * 132 + j + 32];
        Es[r * 132 + j]      = x1 * cs2 - x2 * sn;
        Es[r * 132 + j + 32] = x1 * sn + x2 * cs2;
    }
    // Hadamard (7 butterfly stages)
    for (int step = 1; step < 128; step <<= 1) {
        __syncthreads();
        for (int it = tid; it < 128 * 64; it += 512) {
            int r = it >> 6, pp = it & 63;
            int i = ((pp & ~(step - 1)) << 1) | (pp & (step - 1));
            float a = Es[r * 132 + i], b = Es[r * 132 + i + step];
            Es[r * 132 + i]        = a + b;
            Es[r * 132 + i + step] = a - b;
        }
    }
    __syncthreads();
    for (int it = tid; it < 128 * 128; it += 512) {
        int r = it >> 7, d2 = it & 127;
        outp[(size_t)(m0 + r) * Old + n0 + d2] = __float2bfloat16(Es[r * 132 + d2] * HAD_SCALE);
    }
}

// ---------------------------------------------------------------------------
// w[t][h] = x[t] . Wwt[:,h].  x row shared via smem; Wwt^T for coalescing.
// ---------------------------------------------------------------------------
__global__ __launch_bounds__(256) void w_kernel() {
    __shared__ __nv_bfloat16 xr[D_MODEL];   // 4 KB
    const int t = blockIdx.x;
    const int tid = threadIdx.x;
    // 2048 bf16 = 256 x uint4
    *(uint4*)&xr[tid * 8] = *(const uint4*)&g_xb[(size_t)t * D_MODEL + tid * 8];
    __syncthreads();
    const int warp = tid >> 5, lane = tid & 31;
    const float* wt = g_wwtT + warp * D_MODEL;
    float sum = 0.f;
    #pragma unroll 8
    for (int k = lane; k < D_MODEL; k += 32)
        sum += __bfloat162float(xr[k]) * wt[k];
    #pragma unroll
    for (int o = 16; o > 0; o >>= 1) sum += __shfl_xor_sync(0xffffffffu, sum, o);
    if (lane == 0) g_w[(size_t)t * H + warp] = sum;
}

// ---------------------------------------------------------------------------
// scores: tile 128(t) x 128(s) per CTA, grid (32, 32), 512 threads.
// K-tile resident; per-head Q double-buffered via cp.async.
// dyn smem: Ks 128*272 + Qs 2*128*272 = 104448 B.
// ---------------------------------------------------------------------------
__global__ __launch_bounds__(512) void scores_kernel(float* __restrict__ out) {
    const int s0 = blockIdx.x * 128;
    const int t0 = blockIdx.y * 128;
    const int tid = threadIdx.x;

    if (s0 > t0 + 127) {   // fully masked tile
        const float4 n4 = make_float4(NEG, NEG, NEG, NEG);
        for (int it = tid; it < 128 * 32; it += 512) {
            int r = it >> 5, c = (it & 31) * 4;
            *(float4*)&out[(size_t)(t0 + r) * S_LEN + s0 + c] = n4;
        }
        return;
    }

    extern __shared__ char sm[];
    char* Ks = sm;                          // [128][136] bf16
    __shared__ float ws[128][8];

    const int lane = tid & 31, warp = tid >> 5;
    const int wm = (warp & 3) * 32;
    const int wn = (warp >> 2) * 32;
    const int gid = lane >> 2, tig = lane & 3;

    for (int it = tid; it < 1024; it += 512)
        ws[it >> 3][it & 7] = g_w[(size_t)(t0 + (it >> 3)) * H + (it & 7)];

    #pragma unroll
    for (int i = 0; i < 4; i++) {
        int c = tid + i * 512;
        int r = c >> 4, sg = c & 15;
        cp16(smem_u32(Ks + r * 272 + sg * 16), g_kprime + (size_t)(s0 + r) * D + sg * 8);
    }
    {
        char* Q0 = sm + 34816;
        #pragma unroll
        for (int i = 0; i < 4; i++) {
            int c = tid + i * 512;
            int r = c >> 4, sg = c & 15;
            cp16(smem_u32(Q0 + r * 272 + sg * 16),
                 g_qprime + ((size_t)(t0 + r) * H + 0) * D + sg * 8);
        }
    }
    cp_commit();

    float score[2][4][4];
    #pragma unroll
    for (int mt = 0; mt < 2; mt++)
        #pragma unroll
        for (int nt = 0; nt < 4; nt++)
            #pragma unroll
            for (int j = 0; j < 4; j++) score[mt][nt][j] = 0.f;

    for (int h = 0; h < H; h++) {
        cp_wait<0>();
        __syncthreads();
        if (h < 7) {
            char* Qn = sm + 34816 + ((h + 1) & 1) * 34816;
            #pragma unroll
            for (int i = 0; i < 4; i++) {
                int c = tid + i * 512;
                int r = c >> 4, sg = c & 15;
                cp16(smem_u32(Qn + r * 272 + sg * 16),
                     g_qprime + ((size_t)(t0 + r) * H + h + 1) * D + sg * 8);
            }
            cp_commit();
        }
        const char* Qb = sm + 34816 + (h & 1) * 34816;

        float acc[2][4][4];
        #pragma unroll
        for (int mt = 0; mt < 2; mt++)
            #pragma unroll
            for (int nt = 0; nt < 4; nt++)
                #pragma unroll
                for (int j = 0; j < 4; j++) acc[mt][nt][j] = 0.f;

        #pragma unroll
        for (int kc = 0; kc < 128; kc += 16) {
            uint32_t af[2][4];
            #pragma unroll
            for (int mt = 0; mt < 2; mt++) {
                uint32_t ad = smem_u32(Qb + (wm + mt * 16 + (lane & 15)) * 272
                                          + (kc + 8 * (lane >> 4)) * 2);
                ldmx4(af[mt], ad);
            }
            #pragma unroll
            for (int ng = 0; ng < 2; ng++) {
                uint32_t bf[4];
                int row = wn + ng * 16 + ((lane >> 4) << 3) + (lane & 7);
                int ck  = kc + 8 * ((lane >> 3) & 1);
                ldmx4(bf, smem_u32(Ks + row * 272 + ck * 2));
                #pragma unroll
                for (int mt = 0; mt < 2; mt++) {
                    mma16816(acc[mt][2 * ng],     af[mt], bf + 0);
                    mma16816(acc[mt][2 * ng + 1], af[mt], bf + 2);
                }
            }
        }
        #pragma unroll
        for (int mt = 0; mt < 2; mt++) {
            float w0 = ws[wm + mt * 16 + gid][h];
            float w1 = ws[wm + mt * 16 + 8 + gid][h];
            #pragma unroll
            for (int nt = 0; nt < 4; nt++) {
                score[mt][nt][0] += w0 * fmaxf(acc[mt][nt][0], 0.f);
                score[mt][nt][1] += w0 * fmaxf(acc[mt][nt][1], 0.f);
                score[mt][nt][2] += w1 * fmaxf(acc[mt][nt][2], 0.f);
                score[mt][nt][3] += w1 * fmaxf(acc[mt][nt][3], 0.f);
            }
        }
    }

    #pragma unroll
    for (int mt = 0; mt < 2; mt++) {
        int r0 = t0 + wm + mt * 16 + gid;
        int r1 = r0 + 8;
        #pragma unroll
        for (int nt = 0; nt < 4; nt++) {
            int cs = s0 + wn + nt * 8 + 2 * tig;
            float2 v0, v1;
            v0.x = (cs     <= r0) ? score[mt][nt][0] * HAD_SCALE : NEG;
            v0.y = (cs + 1 <= r0) ? score[mt][nt][1] * HAD_SCALE : NEG;
            v1.x = (cs     <= r1) ? score[mt][nt][2] * HAD_SCALE : NEG;
            v1.y = (cs + 1 <= r1) ? score[mt][nt][3] * HAD_SCALE : NEG;
            *(float2*)&out[(size_t)r0 * S_LEN + cs] = v0;
            *(float2*)&out[(size_t)r1 * S_LEN + cs] = v1;
        }
    }
}

// ---------------------------------------------------------------------------
extern "C" void kernel_launch(void* const* d_in, const int* in_sizes, int n_in,
                              void* d_out, int out_size) {
    const float* x    = (const float*)d_in[0];
    const float* qlat = (const float*)d_in[1];
    const float* Wq   = (const float*)d_in[2];
    const float* Wk   = (const float*)d_in[3];
    const float* ln_g = (const float*)d_in[4];
    const float* ln_b = (const float*)d_in[5];
    const float* Wwt  = (const float*)d_in[6];
    float* out = (float*)d_out;

    void *wqt, *wkt;
    cudaGetSymbolAddress(&wqt, g_wqt);
    cudaGetSymbolAddress(&wkt, g_wkt);

    cudaFuncSetAttribute(proj_kernel,   cudaFuncAttributeMaxDynamicSharedMemorySize, 208896);
    cudaFuncSetAttribute(scores_kernel, cudaFuncAttributeMaxDynamicSharedMemorySize, 104448);

    cvt_all_kernel<<<CVT_BLOCKS, 256>>>(x, qlat);
    tconv_kernel<<<dim3(D_CQ / 32, (H * D) / 32), 256>>>(Wq, (__nv_bfloat16*)wqt, D_CQ, H * D);
    tconv_kernel<<<dim3(D_MODEL / 32, D / 32), 256>>>(Wk, (__nv_bfloat16*)wkt, D_MODEL, D);
    wwt_t_kernel<<<D_MODEL / 256, 256>>>(Wwt);

    proj_kernel<<<dim3(9, S_LEN / 128), 512, 208896>>>(ln_g, ln_b);

    w_kernel<<<S_LEN, 256>>>();

    scores_kernel<<<dim3(S_LEN / 128, S_LEN / 128), 512, 104448>>>(out);
}

// round 11
// speedup vs baseline: 1.2909x; 1.0423x over previous
#include <cuda_runtime.h>
#include <cuda_bf16.h>
#include <stdint.h>

#define S_LEN 4096
#define D_MODEL 2048
#define D_CQ 1536
#define H 8
#define D 128
#define NEG (-1000000000.0f)
#define HAD_SCALE 0.08838834764831845f   // 128^-0.5

// ---------------- scratch (device globals; no allocation allowed) ----------
__device__ __nv_bfloat16 g_qprime[S_LEN * H * D];     // [t][h][d]
__device__ __nv_bfloat16 g_kprime[S_LEN * D];         // [s][d]
__device__ float         g_w[S_LEN * H];              // [t][h]
__device__ __nv_bfloat16 g_xb [S_LEN * D_MODEL];      // x bf16
__device__ __nv_bfloat16 g_qlb[S_LEN * D_CQ];         // q_latent bf16
__device__ __nv_bfloat16 g_wqt[(H * D) * D_CQ];       // Wq^T  [N=1024][K=1536]
__device__ __nv_bfloat16 g_wkt[D * D_MODEL];          // Wk^T  [N=128][K=2048]
__device__ float         g_wwtT[H * D_MODEL];         // Wwt^T [h][k]

// ---------------- asm helpers ---------------------------------------------
__device__ __forceinline__ uint32_t smem_u32(const void* p) {
    return (uint32_t)__cvta_generic_to_shared(p);
}
__device__ __forceinline__ void cp16(uint32_t dst, const void* src) {
    asm volatile("cp.async.cg.shared.global [%0], [%1], 16;\n" :: "r"(dst), "l"(src));
}
__device__ __forceinline__ void cp_commit() {
    asm volatile("cp.async.commit_group;\n" ::: "memory");
}
template<int N> __device__ __forceinline__ void cp_wait() {
    asm volatile("cp.async.wait_group %0;\n" :: "n"(N) : "memory");
}
__device__ __forceinline__ void ldmx4(uint32_t* r, uint32_t a) {
    asm volatile("ldmatrix.sync.aligned.m8n8.x4.shared.b16 {%0,%1,%2,%3}, [%4];\n"
                 : "=r"(r[0]), "=r"(r[1]), "=r"(r[2]), "=r"(r[3]) : "r"(a));
}
__device__ __forceinline__ void mma16816(float c[4], const uint32_t a[4], const uint32_t b[2]) {
    asm volatile(
        "mma.sync.aligned.m16n8k16.row.col.f32.bf16.bf16.f32 "
        "{%0,%1,%2,%3}, {%4,%5,%6,%7}, {%8,%9}, {%0,%1,%2,%3};\n"
        : "+f"(c[0]), "+f"(c[1]), "+f"(c[2]), "+f"(c[3])
        : "r"(a[0]), "r"(a[1]), "r"(a[2]), "r"(a[3]), "r"(b[0]), "r"(b[1]));
}

// ---------------- fused prep kernel ----------------------------------------
// Segments (by blockIdx.x): cvt x | cvt ql | tconv Wq | tconv Wk | wwt^T
#define N_X   (S_LEN * D_MODEL)           // 8388608
#define N_QL  (S_LEN * D_CQ)              // 6291456
#define B_CVTX (N_X / 1024)               // 8192
#define B_CVTQ (N_QL / 1024)              // 6144
#define B_TWQ  ((D_CQ / 32) * ((H * D) / 32))   // 48*32 = 1536
#define B_TWK  ((D_MODEL / 32) * (D / 32))      // 64*4  = 256
#define B_WWT  (D_MODEL / 256)                  // 8
#define PREP_BLOCKS (B_CVTX + B_CVTQ + B_TWQ + B_TWK + B_WWT)

__device__ __forceinline__ void cvt_seg(const float* __restrict__ s,
                                        __nv_bfloat16* __restrict__ d, long j) {
    float4 v = *(const float4*)(s + j);
    __nv_bfloat162 p0 = __floats2bfloat162_rn(v.x, v.y);
    __nv_bfloat162 p1 = __floats2bfloat162_rn(v.z, v.w);
    uint2 u;
    u.x = *(uint32_t*)&p0;
    u.y = *(uint32_t*)&p1;
    *(uint2*)(d + j) = u;
}

__device__ __forceinline__ void tconv_seg(const float* __restrict__ src,
                                          __nv_bfloat16* __restrict__ dst,
                                          int K, int N, int k0, int n0,
                                          float (*t)[33]) {
    const int tx = threadIdx.x & 31, ty = threadIdx.x >> 5;  // 32 x 8
    #pragma unroll
    for (int i = 0; i < 4; i++)
        t[ty + 8 * i][tx] = src[(size_t)(k0 + ty + 8 * i) * N + n0 + tx];
    __syncthreads();
    #pragma unroll
    for (int i = 0; i < 4; i++)
        dst[(size_t)(n0 + ty + 8 * i) * K + k0 + tx] = __float2bfloat16(t[tx][ty + 8 * i]);
}

__global__ __launch_bounds__(256) void prep_kernel(const float* __restrict__ x,
                                                   const float* __restrict__ ql,
                                                   const float* __restrict__ Wq,
                                                   const float* __restrict__ Wk,
                                                   const float* __restrict__ Wwt) {
    __shared__ float t[32][33];
    int b = blockIdx.x;
    if (b < B_CVTX) {
        cvt_seg(x, g_xb, ((long)b * 256 + threadIdx.x) * 4);
        return;
    }
    b -= B_CVTX;
    if (b < B_CVTQ) {
        cvt_seg(ql, g_qlb, ((long)b * 256 + threadIdx.x) * 4);
        return;
    }
    b -= B_CVTQ;
    if (b < B_TWQ) {
        int k0 = (b % (D_CQ / 32)) * 32;
        int n0 = (b / (D_CQ / 32)) * 32;
        tconv_seg(Wq, g_wqt, D_CQ, H * D, k0, n0, t);
        return;
    }
    b -= B_TWQ;
    if (b < B_TWK) {
        int k0 = (b % (D_MODEL / 32)) * 32;
        int n0 = (b / (D_MODEL / 32)) * 32;
        tconv_seg(Wk, g_wkt, D_MODEL, D, k0, n0, t);
        return;
    }
    b -= B_TWK;
    {
        int k = b * 256 + threadIdx.x;
        #pragma unroll
        for (int h = 0; h < H; h++)
            g_wwtT[h * D_MODEL + k] = Wwt[(size_t)k * H + h];
    }
}

// ---------------------------------------------------------------------------
// Merged projection GEMM (mma.sync, 3-stage cp.async ring, 1 sync/chunk).
// grid (9, 32): blockIdx.x 0..7 -> Q head tiles, 8 -> K tile (+LayerNorm).
// 512 threads, 128x128 tile, warp tile 32x32, K chunks of 128.
// dyn smem: 3 stages x (A 34816 + B 34816) = 208896 B; Es[128][132] aliases.
// ---------------------------------------------------------------------------
__global__ __launch_bounds__(512, 1) void proj_kernel(const float* __restrict__ ln_g,
                                                      const float* __restrict__ ln_b) {
    extern __shared__ char sm[];
    __shared__ float s_mu[128], s_rs[128];

    const int tile = blockIdx.x;
    const bool isK = (tile == 8);
    const __nv_bfloat16* A  = isK ? g_xb  : g_qlb;   // [4096][Kdim]
    const __nv_bfloat16* Bt = isK ? g_wkt : g_wqt;   // [N][Kdim]
    const int Kdim = isK ? D_MODEL : D_CQ;
    const int n0   = isK ? 0 : tile * 128;
    __nv_bfloat16* outp = isK ? g_kprime : g_qprime;
    const int Old  = isK ? D : (H * D);
    const int m0 = blockIdx.y * 128;

    const int tid = threadIdx.x, lane = tid & 31, warp = tid >> 5;
    const int wm = (warp & 3) * 32;          // 4 m-warps
    const int wn = (warp >> 2) * 32;         // 4 n-warps
    const int gid = lane >> 2, tig = lane & 3;

    const int KT = Kdim >> 7;                // chunks of 128

    auto fill = [&](int st, int k0) {
        char* as = sm + st * 69632;
        char* bs = as + 34816;
        #pragma unroll
        for (int i = 0; i < 4; i++) {
            int c = tid + i * 512;
            int r = c >> 4, g = c & 15;
            cp16(smem_u32(as + r * 272 + g * 16), A  + (size_t)(m0 + r) * Kdim + k0 + g * 8);
        }
        #pragma unroll
        for (int i = 0; i < 4; i++) {
            int c = tid + i * 512;
            int r = c >> 4, g = c & 15;
            cp16(smem_u32(bs + r * 272 + g * 16), Bt + (size_t)(n0 + r) * Kdim + k0 + g * 8);
        }
    };

    float acc[2][4][4];
    #pragma unroll
    for (int mt = 0; mt < 2; mt++)
        #pragma unroll
        for (int nt = 0; nt < 4; nt++)
            #pragma unroll
            for (int j = 0; j < 4; j++) acc[mt][nt][j] = 0.f;

    fill(0, 0);   cp_commit();
    fill(1, 128); cp_commit();

    int cs_ = 0;                   // compute slot = kt % 3
    for (int kt = 0; kt < KT; kt++) {
        cp_wait<1>();
        __syncthreads();           // slot (kt+2)%3 == (kt-1)%3 now free for refill
        if (kt + 2 < KT) {
            int fs = cs_ + 2; if (fs >= 3) fs -= 3;
            fill(fs, (kt + 2) * 128);
        }
        cp_commit();               // one group per iteration (possibly empty)

        const char* as = sm + cs_ * 69632;
        const char* bs = as + 34816;
        #pragma unroll
        for (int kc = 0; kc < 128; kc += 16) {
            uint32_t af[2][4];
            #pragma unroll
            for (int mt = 0; mt < 2; mt++) {
                uint32_t ad = smem_u32(as + (wm + mt * 16 + (lane & 15)) * 272
                                          + (kc + 8 * (lane >> 4)) * 2);
                ldmx4(af[mt], ad);
            }
            #pragma unroll
            for (int ng = 0; ng < 2; ng++) {
                uint32_t bf[4];
                int row = wn + ng * 16 + ((lane >> 4) << 3) + (lane & 7);
                int ck  = kc + 8 * ((lane >> 3) & 1);
                ldmx4(bf, smem_u32(bs + row * 272 + ck * 2));
                #pragma unroll
                for (int mt = 0; mt < 2; mt++) {
                    mma16816(acc[mt][2 * ng],     af[mt], bf + 0);
                    mma16816(acc[mt][2 * ng + 1], af[mt], bf + 2);
                }
            }
        }
        if (++cs_ == 3) cs_ = 0;
    }
    cp_wait<0>();
    __syncthreads();

    // ---- epilogue: acc -> Es (fp32, aliases stage buffers) ----
    float* Es = (float*)sm;    // [128][132]
    #pragma unroll
    for (int mt = 0; mt < 2; mt++) {
        int r0 = wm + mt * 16 + gid;
        int r1 = r0 + 8;
        #pragma unroll
        for (int nt = 0; nt < 4; nt++) {
            int c = wn + nt * 8 + 2 * tig;
            Es[r0 * 132 + c]     = acc[mt][nt][0];
            Es[r0 * 132 + c + 1] = acc[mt][nt][1];
            Es[r1 * 132 + c]     = acc[mt][nt][2];
            Es[r1 * 132 + c + 1] = acc[mt][nt][3];
        }
    }
    __syncthreads();

    if (isK) {
        if (tid < 128) {
            float sum = 0.f, sq = 0.f;
            #pragma unroll 4
            for (int d2 = 0; d2 < 128; d2++) {
                float v = Es[tid * 132 + d2];
                sum += v; sq += v * v;
            }
            float mu  = sum * (1.0f / 128.0f);
            float var = sq * (1.0f / 128.0f) - mu * mu;
            s_mu[tid] = mu;
            s_rs[tid] = rsqrtf(var + 1e-5f);
        }
        __syncthreads();
        for (int it = tid; it < 128 * 128; it += 512) {
            int r = it >> 7, d2 = it & 127;
            Es[r * 132 + d2] = (Es[r * 132 + d2] - s_mu[r]) * s_rs[r] * ln_g[d2] + ln_b[d2];
        }
        __syncthreads();
    }
    // RoPE: pairs (j, j+32), j<32; freq = 10000^(-j/32)
    for (int it = tid; it < 128 * 32; it += 512) {
        int r = it >> 5, j = it & 31;
        float t = (float)(m0 + r);
        float freq = exp2f((float)j * (-0.41524101186092029f));
        float sn, cs2;
        sincosf(t * freq, &sn, &cs2);
        float x1 = Es[r * 132 + j], x2 = Es[r * 132 + j + 32];
        Es[r * 132 + j]      = x1 * cs2 - x2 * sn;
        Es[r * 132 + j + 32] = x1 * sn + x2 * cs2;
    }
    // Hadamard (7 butterfly stages)
    for (int step = 1; step < 128; step <<= 1) {
        __syncthreads();
        for (int it = tid; it < 128 * 64; it += 512) {
            int r = it >> 6, pp = it & 63;
            int i = ((pp & ~(step - 1)) << 1) | (pp & (step - 1));
            float a = Es[r * 132 + i], b = Es[r * 132 + i + step];
            Es[r * 132 + i]        = a + b;
            Es[r * 132 + i + step] = a - b;
        }
    }
    __syncthreads();
    for (int it = tid; it < 128 * 128; it += 512) {
        int r = it >> 7, d2 = it & 127;
        outp[(size_t)(m0 + r) * Old + n0 + d2] = __float2bfloat16(Es[r * 132 + d2] * HAD_SCALE);
    }
}

// ---------------------------------------------------------------------------
// w[t][h] = x[t] . Wwt[:,h].  x row shared via smem; Wwt^T for coalescing.
// ---------------------------------------------------------------------------
__global__ __launch_bounds__(256) void w_kernel() {
    __shared__ __nv_bfloat16 xr[D_MODEL];   // 4 KB
    const int t = blockIdx.x;
    const int tid = threadIdx.x;
    *(uint4*)&xr[tid * 8] = *(const uint4*)&g_xb[(size_t)t * D_MODEL + tid * 8];
    __syncthreads();
    const int warp = tid >> 5, lane = tid & 31;
    const float* wt = g_wwtT + warp * D_MODEL;
    float sum = 0.f;
    #pragma unroll 8
    for (int k = lane; k < D_MODEL; k += 32)
        sum += __bfloat162float(xr[k]) * wt[k];
    #pragma unroll
    for (int o = 16; o > 0; o >>= 1) sum += __shfl_xor_sync(0xffffffffu, sum, o);
    if (lane == 0) g_w[(size_t)t * H + warp] = sum;
}

// ---------------------------------------------------------------------------
// scores: tile 128(t) x 128(s) per CTA, grid (32, 32), 512 threads.
// K-tile resident; per-head Q TRIPLE-buffered (cp_wait<1>, 1 sync/head).
// dyn smem: Ks 34816 + Qs 3*34816 = 139264 B.
// ---------------------------------------------------------------------------
__global__ __launch_bounds__(512, 1) void scores_kernel(float* __restrict__ out) {
    const int s0 = blockIdx.x * 128;
    const int t0 = blockIdx.y * 128;
    const int tid = threadIdx.x;

    if (s0 > t0 + 127) {   // fully masked tile
        const float4 n4 = make_float4(NEG, NEG, NEG, NEG);
        for (int it = tid; it < 128 * 32; it += 512) {
            int r = it >> 5, c = (it & 31) * 4;
            *(float4*)&out[(size_t)(t0 + r) * S_LEN + s0 + c] = n4;
        }
        return;
    }

    extern __shared__ char sm[];
    char* Ks = sm;                          // [128][136] bf16
    char* Qs = sm + 34816;                  // 3 slots x [128][136]
    __shared__ float ws[128][8];

    const int lane = tid & 31, warp = tid >> 5;
    const int wm = (warp & 3) * 32;
    const int wn = (warp >> 2) * 32;
    const int gid = lane >> 2, tig = lane & 3;

    auto fillQ = [&](int slot, int h) {
        char* Qn = Qs + slot * 34816;
        #pragma unroll
        for (int i = 0; i < 4; i++) {
            int c = tid + i * 512;
            int r = c >> 4, sg = c & 15;
            cp16(smem_u32(Qn + r * 272 + sg * 16),
                 g_qprime + ((size_t)(t0 + r) * H + h) * D + sg * 8);
        }
    };

    for (int it = tid; it < 1024; it += 512)
        ws[it >> 3][it & 7] = g_w[(size_t)(t0 + (it >> 3)) * H + (it & 7)];

    #pragma unroll
    for (int i = 0; i < 4; i++) {           // K tile 128x128 bf16
        int c = tid + i * 512;
        int r = c >> 4, sg = c & 15;
        cp16(smem_u32(Ks + r * 272 + sg * 16), g_kprime + (size_t)(s0 + r) * D + sg * 8);
    }
    fillQ(0, 0); cp_commit();               // G0 = K + Q0
    fillQ(1, 1); cp_commit();               // G1 = Q1

    float score[2][4][4];
    #pragma unroll
    for (int mt = 0; mt < 2; mt++)
        #pragma unroll
        for (int nt = 0; nt < 4; nt++)
            #pragma unroll
            for (int j = 0; j < 4; j++) score[mt][nt][j] = 0.f;

    int qs_ = 0;                            // compute slot = h % 3
    for (int h = 0; h < H; h++) {
        cp_wait<1>();
        __syncthreads();                    // slot (h+2)%3 (held head h-1) now free
        if (h + 2 < H) {
            int fs = qs_ + 2; if (fs >= 3) fs -= 3;
            fillQ(fs, h + 2);
        }
        cp_commit();                        // one group per iteration

        const char* Qb = Qs + qs_ * 34816;

        float acc[2][4][4];
        #pragma unroll
        for (int mt = 0; mt < 2; mt++)
            #pragma unroll
            for (int nt = 0; nt < 4; nt++)
                #pragma unroll
                for (int j = 0; j < 4; j++) acc[mt][nt][j] = 0.f;

        #pragma unroll
        for (int kc = 0; kc < 128; kc += 16) {
            uint32_t af[2][4];
            #pragma unroll
            for (int mt = 0; mt < 2; mt++) {
                uint32_t ad = smem_u32(Qb + (wm + mt * 16 + (lane & 15)) * 272
                                          + (kc + 8 * (lane >> 4)) * 2);
                ldmx4(af[mt], ad);
            }
            #pragma unroll
            for (int ng = 0; ng < 2; ng++) {
                uint32_t bf[4];
                int row = wn + ng * 16 + ((lane >> 4) << 3) + (lane & 7);
                int ck  = kc + 8 * ((lane >> 3) & 1);
                ldmx4(bf, smem_u32(Ks + row * 272 + ck * 2));
                #pragma unroll
                for (int mt = 0; mt < 2; mt++) {
                    mma16816(acc[mt][2 * ng],     af[mt], bf + 0);
                    mma16816(acc[mt][2 * ng + 1], af[mt], bf + 2);
                }
            }
        }
        #pragma unroll
        for (int mt = 0; mt < 2; mt++) {
            float w0 = ws[wm + mt * 16 + gid][h];
            float w1 = ws[wm + mt * 16 + 8 + gid][h];
            #pragma unroll
            for (int nt = 0; nt < 4; nt++) {
                score[mt][nt][0] += w0 * fmaxf(acc[mt][nt][0], 0.f);
                score[mt][nt][1] += w0 * fmaxf(acc[mt][nt][1], 0.f);
                score[mt][nt][2] += w1 * fmaxf(acc[mt][nt][2], 0.f);
                score[mt][nt][3] += w1 * fmaxf(acc[mt][nt][3], 0.f);
            }
        }
        if (++qs_ == 3) qs_ = 0;
    }

    #pragma unroll
    for (int mt = 0; mt < 2; mt++) {
        int r0 = t0 + wm + mt * 16 + gid;
        int r1 = r0 + 8;
        #pragma unroll
        for (int nt = 0; nt < 4; nt++) {
            int cs = s0 + wn + nt * 8 + 2 * tig;
            float2 v0, v1;
            v0.x = (cs     <= r0) ? score[mt][nt][0] * HAD_SCALE : NEG;
            v0.y = (cs + 1 <= r0) ? score[mt][nt][1] * HAD_SCALE : NEG;
            v1.x = (cs     <= r1) ? score[mt][nt][2] * HAD_SCALE : NEG;
            v1.y = (cs + 1 <= r1) ? score[mt][nt][3] * HAD_SCALE : NEG;
            *(float2*)&out[(size_t)r0 * S_LEN + cs] = v0;
            *(float2*)&out[(size_t)r1 * S_LEN + cs] = v1;
        }
    }
}

// ---------------------------------------------------------------------------
extern "C" void kernel_launch(void* const* d_in, const int* in_sizes, int n_in,
                              void* d_out, int out_size) {
    const float* x    = (const float*)d_in[0];
    const float* qlat = (const float*)d_in[1];
    const float* Wq   = (const float*)d_in[2];
    const float* Wk   = (const float*)d_in[3];
    const float* ln_g = (const float*)d_in[4];
    const float* ln_b = (const float*)d_in[5];
    const float* Wwt  = (const float*)d_in[6];
    float* out = (float*)d_out;

    cudaFuncSetAttribute(proj_kernel,   cudaFuncAttributeMaxDynamicSharedMemorySize, 208896);
    cudaFuncSetAttribute(scores_kernel, cudaFuncAttributeMaxDynamicSharedMemorySize, 139264);

    prep_kernel<<<PREP_BLOCKS, 256>>>(x, qlat, Wq, Wk, Wwt);

    proj_kernel<<<dim3(9, S_LEN / 128), 512, 208896>>>(ln_g, ln_b);

    w_kernel<<<S_LEN, 256>>>();

    scores_kernel<<<dim3(S_LEN / 128, S_LEN / 128), 512, 139264>>>(out);
}

// round 12
// speedup vs baseline: 1.3305x; 1.0306x over previous
#include <cuda_runtime.h>
#include <cuda_bf16.h>
#include <stdint.h>

#define S_LEN 4096
#define D_MODEL 2048
#define D_CQ 1536
#define H 8
#define D 128
#define NEG (-1000000000.0f)
#define HAD_SCALE 0.08838834764831845f   // 128^-0.5

// ---------------- scratch (device globals; no allocation allowed) ----------
__device__ uint8_t g_qp8[S_LEN * H * D];        // q' e4m3 [t][h][d]
__device__ uint8_t g_kp8[S_LEN * D];            // k' e4m3 [s][d]
__device__ float   g_w[S_LEN * H];              // [t][h]
__device__ uint8_t g_x8 [S_LEN * D_MODEL];      // x e4m3
__device__ uint8_t g_ql8[S_LEN * D_CQ];         // q_latent e4m3
__device__ uint8_t g_wqt8[(H * D) * D_CQ];      // Wq^T e4m3 [N=1024][K=1536]
__device__ uint8_t g_wkt8[D * D_MODEL];         // Wk^T e4m3 [N=128][K=2048]
__device__ float   g_wwtT[H * D_MODEL];         // Wwt^T [h][k]

// ---------------- asm helpers ---------------------------------------------
__device__ __forceinline__ uint32_t smem_u32(const void* p) {
    return (uint32_t)__cvta_generic_to_shared(p);
}
__device__ __forceinline__ void cp16(uint32_t dst, const void* src) {
    asm volatile("cp.async.cg.shared.global [%0], [%1], 16;\n" :: "r"(dst), "l"(src));
}
__device__ __forceinline__ void cp_commit() {
    asm volatile("cp.async.commit_group;\n" ::: "memory");
}
template<int N> __device__ __forceinline__ void cp_wait() {
    asm volatile("cp.async.wait_group %0;\n" :: "n"(N) : "memory");
}
__device__ __forceinline__ void ldmx4(uint32_t* r, uint32_t a) {
    asm volatile("ldmatrix.sync.aligned.m8n8.x4.shared.b16 {%0,%1,%2,%3}, [%4];\n"
                 : "=r"(r[0]), "=r"(r[1]), "=r"(r[2]), "=r"(r[3]) : "r"(a));
}
// fp8 e4m3 mma: D(fp32) += A(e4m3) * B(e4m3), m16n8k32
__device__ __forceinline__ void mma16832(float c[4], const uint32_t a[4], const uint32_t b[2]) {
    asm volatile(
        "mma.sync.aligned.m16n8k32.row.col.f32.e4m3.e4m3.f32 "
        "{%0,%1,%2,%3}, {%4,%5,%6,%7}, {%8,%9}, {%0,%1,%2,%3};\n"
        : "+f"(c[0]), "+f"(c[1]), "+f"(c[2]), "+f"(c[3])
        : "r"(a[0]), "r"(a[1]), "r"(a[2]), "r"(a[3]), "r"(b[0]), "r"(b[1]));
}
// pack two floats -> e4m3x2 (low byte = lo)
__device__ __forceinline__ uint32_t pk2(float lo, float hi) {
    uint16_t r;
    asm("cvt.rn.satfinite.e4m3x2.f32 %0, %1, %2;" : "=h"(r) : "f"(hi), "f"(lo));
    return (uint32_t)r;
}

// ---------------- fused prep kernel ----------------------------------------
// Segments (blockIdx.x): cvt x | cvt ql | tconv Wq | tconv Wk | wwt^T
#define N_X   (S_LEN * D_MODEL)           // 8388608
#define N_QL  (S_LEN * D_CQ)              // 6291456
#define B_CVTX (N_X / 2048)               // 4096
#define B_CVTQ (N_QL / 2048)              // 3072
#define B_TWQ  ((D_CQ / 32) * ((H * D) / 32))   // 1536
#define B_TWK  ((D_MODEL / 32) * (D / 32))      // 256
#define B_WWT  (D_MODEL / 256)                  // 8
#define PREP_BLOCKS (B_CVTX + B_CVTQ + B_TWQ + B_TWK + B_WWT)

__device__ __forceinline__ void cvt8_seg(const float* __restrict__ s,
                                         uint8_t* __restrict__ d, long j) {
    float4 v0 = *(const float4*)(s + j);
    float4 v1 = *(const float4*)(s + j + 4);
    uint2 u;
    u.x = pk2(v0.x, v0.y) | (pk2(v0.z, v0.w) << 16);
    u.y = pk2(v1.x, v1.y) | (pk2(v1.z, v1.w) << 16);
    *(uint2*)(d + j) = u;
}

__device__ __forceinline__ void tconv8_seg(const float* __restrict__ src,
                                           uint8_t* __restrict__ dst,
                                           int K, int N, int k0, int n0,
                                           float (*t)[33]) {
    const int tx = threadIdx.x & 31, ty = threadIdx.x >> 5;  // 32 x 8
    #pragma unroll
    for (int i = 0; i < 4; i++)
        t[ty + 8 * i][tx] = src[(size_t)(k0 + ty + 8 * i) * N + n0 + tx];
    __syncthreads();
    const int nr = threadIdx.x >> 3;          // 0..31 output row (n)
    const int kq = (threadIdx.x & 7) * 4;     // k quad
    uint32_t w = pk2(t[kq][nr], t[kq + 1][nr]) | (pk2(t[kq + 2][nr], t[kq + 3][nr]) << 16);
    *(uint32_t*)&dst[(size_t)(n0 + nr) * K + k0 + kq] = w;
}

__global__ __launch_bounds__(256) void prep_kernel(const float* __restrict__ x,
                                                   const float* __restrict__ ql,
                                                   const float* __restrict__ Wq,
                                                   const float* __restrict__ Wk,
                                                   const float* __restrict__ Wwt) {
    __shared__ float t[32][33];
    int b = blockIdx.x;
    if (b < B_CVTX) {
        cvt8_seg(x, g_x8, ((long)b * 256 + threadIdx.x) * 8);
        return;
    }
    b -= B_CVTX;
    if (b < B_CVTQ) {
        cvt8_seg(ql, g_ql8, ((long)b * 256 + threadIdx.x) * 8);
        return;
    }
    b -= B_CVTQ;
    if (b < B_TWQ) {
        int k0 = (b % (D_CQ / 32)) * 32;
        int n0 = (b / (D_CQ / 32)) * 32;
        tconv8_seg(Wq, g_wqt8, D_CQ, H * D, k0, n0, t);
        return;
    }
    b -= B_TWQ;
    if (b < B_TWK) {
        int k0 = (b % (D_MODEL / 32)) * 32;
        int n0 = (b / (D_MODEL / 32)) * 32;
        tconv8_seg(Wk, g_wkt8, D_MODEL, D, k0, n0, t);
        return;
    }
    b -= B_TWK;
    {
        int k = b * 256 + threadIdx.x;
        #pragma unroll
        for (int h = 0; h < H; h++)
            g_wwtT[h * D_MODEL + k] = Wwt[(size_t)k * H + h];
    }
}

// ---------------------------------------------------------------------------
// Merged projection GEMM (fp8 e4m3 mma.sync, 3-stage cp.async ring).
// grid (9, 32): blockIdx.x 0..7 -> Q head tiles, 8 -> K tile (+LayerNorm).
// 512 threads, 128x128 tile, warp tile 32x32, K chunks of 256 e4m3 (256B rows,
// 272B stride). dyn smem: 3 x (34816 + 34816) = 208896; Es[128][132] aliases.
// ---------------------------------------------------------------------------
__global__ __launch_bounds__(512, 1) void proj_kernel(const float* __restrict__ ln_g,
                                                      const float* __restrict__ ln_b) {
    extern __shared__ char sm[];
    __shared__ float s_mu[128], s_rs[128];

    const int tile = blockIdx.x;
    const bool isK = (tile == 8);
    const uint8_t* A  = isK ? g_x8   : g_ql8;    // [4096][Kdim] bytes
    const uint8_t* Bt = isK ? g_wkt8 : g_wqt8;   // [N][Kdim] bytes
    const int Kdim = isK ? D_MODEL : D_CQ;
    const int n0   = isK ? 0 : tile * 128;
    uint8_t* outp  = isK ? g_kp8 : g_qp8;
    const int Old  = isK ? D : (H * D);
    const int m0 = blockIdx.y * 128;

    const int tid = threadIdx.x, lane = tid & 31, warp = tid >> 5;
    const int wm = (warp & 3) * 32;          // 4 m-warps
    const int wn = (warp >> 2) * 32;         // 4 n-warps
    const int gid = lane >> 2, tig = lane & 3;

    const int KT = Kdim >> 8;                // chunks of 256 bytes

    auto fill = [&](int st, int k0) {
        char* as = sm + st * 69632;
        char* bs = as + 34816;
        #pragma unroll
        for (int i = 0; i < 4; i++) {
            int c = tid + i * 512;
            int r = c >> 4, g = c & 15;
            cp16(smem_u32(as + r * 272 + g * 16), A  + (size_t)(m0 + r) * Kdim + k0 + g * 16);
        }
        #pragma unroll
        for (int i = 0; i < 4; i++) {
            int c = tid + i * 512;
            int r = c >> 4, g = c & 15;
            cp16(smem_u32(bs + r * 272 + g * 16), Bt + (size_t)(n0 + r) * Kdim + k0 + g * 16);
        }
    };

    float acc[2][4][4];
    #pragma unroll
    for (int mt = 0; mt < 2; mt++)
        #pragma unroll
        for (int nt = 0; nt < 4; nt++)
            #pragma unroll
            for (int j = 0; j < 4; j++) acc[mt][nt][j] = 0.f;

    fill(0, 0);   cp_commit();
    fill(1, 256); cp_commit();

    int cs_ = 0;                   // compute slot = kt % 3
    for (int kt = 0; kt < KT; kt++) {
        cp_wait<1>();
        __syncthreads();           // slot (kt+2)%3 == (kt-1)%3 now free for refill
        if (kt + 2 < KT) {
            int fs = cs_ + 2; if (fs >= 3) fs -= 3;
            fill(fs, (kt + 2) * 256);
        }
        cp_commit();               // one group per iteration (possibly empty)

        const char* as = sm + cs_ * 69632;
        const char* bs = as + 34816;
        #pragma unroll
        for (int kc = 0; kc < 256; kc += 32) {        // 8 k32 steps
            uint32_t af[2][4];
            #pragma unroll
            for (int mt = 0; mt < 2; mt++) {
                uint32_t ad = smem_u32(as + (wm + mt * 16 + (lane & 15)) * 272
                                          + kc + 16 * (lane >> 4));
                ldmx4(af[mt], ad);
            }
            #pragma unroll
            for (int ng = 0; ng < 2; ng++) {
                uint32_t bf[4];
                int row = wn + ng * 16 + ((lane >> 4) << 3) + (lane & 7);
                int ckb = kc + 16 * ((lane >> 3) & 1);
                ldmx4(bf, smem_u32(bs + row * 272 + ckb));
                #pragma unroll
                for (int mt = 0; mt < 2; mt++) {
                    mma16832(acc[mt][2 * ng],     af[mt], bf + 0);
                    mma16832(acc[mt][2 * ng + 1], af[mt], bf + 2);
                }
            }
        }
        if (++cs_ == 3) cs_ = 0;
    }
    cp_wait<0>();
    __syncthreads();

    // ---- epilogue: acc -> Es (fp32, aliases stage buffers) ----
    float* Es = (float*)sm;    // [128][132]
    #pragma unroll
    for (int mt = 0; mt < 2; mt++) {
        int r0 = wm + mt * 16 + gid;
        int r1 = r0 + 8;
        #pragma unroll
        for (int nt = 0; nt < 4; nt++) {
            int c = wn + nt * 8 + 2 * tig;
            Es[r0 * 132 + c]     = acc[mt][nt][0];
            Es[r0 * 132 + c + 1] = acc[mt][nt][1];
            Es[r1 * 132 + c]     = acc[mt][nt][2];
            Es[r1 * 132 + c + 1] = acc[mt][nt][3];
        }
    }
    __syncthreads();

    if (isK) {
        if (tid < 128) {
            float sum = 0.f, sq = 0.f;
            #pragma unroll 4
            for (int d2 = 0; d2 < 128; d2++) {
                float v = Es[tid * 132 + d2];
                sum += v; sq += v * v;
            }
            float mu  = sum * (1.0f / 128.0f);
            float var = sq * (1.0f / 128.0f) - mu * mu;
            s_mu[tid] = mu;
            s_rs[tid] = rsqrtf(var + 1e-5f);
        }
        __syncthreads();
        for (int it = tid; it < 128 * 128; it += 512) {
            int r = it >> 7, d2 = it & 127;
            Es[r * 132 + d2] = (Es[r * 132 + d2] - s_mu[r]) * s_rs[r] * ln_g[d2] + ln_b[d2];
        }
        __syncthreads();
    }
    // RoPE: pairs (j, j+32), j<32; freq = 10000^(-j/32)
    for (int it = tid; it < 128 * 32; it += 512) {
        int r = it >> 5, j = it & 31;
        float t = (float)(m0 + r);
        float freq = exp2f((float)j * (-0.41524101186092029f));
        float sn, cs2;
        sincosf(t * freq, &sn, &cs2);
        float x1 = Es[r * 132 + j], x2 = Es[r * 132 + j + 32];
        Es[r * 132 + j]      = x1 * cs2 - x2 * sn;
        Es[r * 132 + j + 32] = x1 * sn + x2 * cs2;
    }
    // Hadamard (7 butterfly stages)
    for (int step = 1; step < 128; step <<= 1) {
        __syncthreads();
        for (int it = tid; it < 128 * 64; it += 512) {
            int r = it >> 6, pp = it & 63;
            int i = ((pp & ~(step - 1)) << 1) | (pp & (step - 1));
            float a = Es[r * 132 + i], b = Es[r * 132 + i + step];
            Es[r * 132 + i]        = a + b;
            Es[r * 132 + i + step] = a - b;
        }
    }
    __syncthreads();
    // pack fp8 output (4 bytes per thread per iter)
    for (int it = tid; it < 128 * 32; it += 512) {
        int r = it >> 5, q4 = (it & 31) * 4;
        float e0 = Es[r * 132 + q4]     * HAD_SCALE;
        float e1 = Es[r * 132 + q4 + 1] * HAD_SCALE;
        float e2 = Es[r * 132 + q4 + 2] * HAD_SCALE;
        float e3 = Es[r * 132 + q4 + 3] * HAD_SCALE;
        uint32_t wv = pk2(e0, e1) | (pk2(e2, e3) << 16);
        *(uint32_t*)&outp[(size_t)(m0 + r) * Old + n0 + q4] = wv;
    }
}

// ---------------------------------------------------------------------------
// w[t][h] = x[t] . Wwt[:,h].  fp32 x row staged via smem; Wwt^T coalesced.
// ---------------------------------------------------------------------------
__global__ __launch_bounds__(256) void w_kernel(const float* __restrict__ x) {
    __shared__ float xr[D_MODEL];   // 8 KB
    const int t = blockIdx.x;
    const int tid = threadIdx.x;
    *(float4*)&xr[tid * 8]     = *(const float4*)&x[(size_t)t * D_MODEL + tid * 8];
    *(float4*)&xr[tid * 8 + 4] = *(const float4*)&x[(size_t)t * D_MODEL + tid * 8 + 4];
    __syncthreads();
    const int warp = tid >> 5, lane = tid & 31;
    const float* wt = g_wwtT + warp * D_MODEL;
    float sum = 0.f;
    #pragma unroll 8
    for (int k = lane; k < D_MODEL; k += 32)
        sum += xr[k] * wt[k];
    #pragma unroll
    for (int o = 16; o > 0; o >>= 1) sum += __shfl_xor_sync(0xffffffffu, sum, o);
    if (lane == 0) g_w[(size_t)t * H + warp] = sum;
}

// ---------------------------------------------------------------------------
// scores: tile 128(t) x 128(s), grid (32, 32), 512 threads. fp8 e4m3 mma.
// K-tile resident; per-head Q TRIPLE-buffered (cp_wait<1>, 1 sync/head).
// fp8 rows: 128B data + 16B pad = 144B. dyn smem: 4 x 18432 = 73728 B.
// ---------------------------------------------------------------------------
__global__ __launch_bounds__(512, 1) void scores_kernel(float* __restrict__ out) {
    const int s0 = blockIdx.x * 128;
    const int t0 = blockIdx.y * 128;
    const int tid = threadIdx.x;

    if (s0 > t0 + 127) {   // fully masked tile
        const float4 n4 = make_float4(NEG, NEG, NEG, NEG);
        for (int it = tid; it < 128 * 32; it += 512) {
            int r = it >> 5, c = (it & 31) * 4;
            *(float4*)&out[(size_t)(t0 + r) * S_LEN + s0 + c] = n4;
        }
        return;
    }

    extern __shared__ char sm[];
    char* Ks = sm;                          // [128][144B]
    char* Qs = sm + 18432;                  // 3 slots x [128][144B]
    __shared__ float ws[128][8];

    const int lane = tid & 31, warp = tid >> 5;
    const int wm = (warp & 3) * 32;
    const int wn = (warp >> 2) * 32;
    const int gid = lane >> 2, tig = lane & 3;

    auto fillQ = [&](int slot, int h) {
        char* Qn = Qs + slot * 18432;
        #pragma unroll
        for (int i = 0; i < 2; i++) {
            int c = tid + i * 512;
            int r = c >> 3, g = c & 7;
            cp16(smem_u32(Qn + r * 144 + g * 16),
                 g_qp8 + (size_t)(t0 + r) * (H * D) + h * D + g * 16);
        }
    };

    for (int it = tid; it < 1024; it += 512)
        ws[it >> 3][it & 7] = g_w[(size_t)(t0 + (it >> 3)) * H + (it & 7)];

    #pragma unroll
    for (int i = 0; i < 2; i++) {           // K tile 128x128 e4m3
        int c = tid + i * 512;
        int r = c >> 3, g = c & 7;
        cp16(smem_u32(Ks + r * 144 + g * 16), g_kp8 + (size_t)(s0 + r) * D + g * 16);
    }
    fillQ(0, 0); cp_commit();               // G0 = K + Q0
    fillQ(1, 1); cp_commit();               // G1 = Q1

    float score[2][4][4];
    #pragma unroll
    for (int mt = 0; mt < 2; mt++)
        #pragma unroll
        for (int nt = 0; nt < 4; nt++)
            #pragma unroll
            for (int j = 0; j < 4; j++) score[mt][nt][j] = 0.f;

    int qs_ = 0;                            // compute slot = h % 3
    for (int h = 0; h < H; h++) {
        cp_wait<1>();
        __syncthreads();                    // slot (h+2)%3 (held head h-1) now free
        if (h + 2 < H) {
            int fs = qs_ + 2; if (fs >= 3) fs -= 3;
            fillQ(fs, h + 2);
        }
        cp_commit();                        // one group per iteration

        const char* Qb = Qs + qs_ * 18432;

        float acc[2][4][4];
        #pragma unroll
        for (int mt = 0; mt < 2; mt++)
            #pragma unroll
            for (int nt = 0; nt < 4; nt++)
                #pragma unroll
                for (int j = 0; j < 4; j++) acc[mt][nt][j] = 0.f;

        #pragma unroll
        for (int kc = 0; kc < 128; kc += 32) {        // 4 k32 steps
            uint32_t af[2][4];
            #pragma unroll
            for (int mt = 0; mt < 2; mt++) {
                uint32_t ad = smem_u32(Qb + (wm + mt * 16 + (lane & 15)) * 144
                                          + kc + 16 * (lane >> 4));
                ldmx4(af[mt], ad);
            }
            #pragma unroll
            for (int ng = 0; ng < 2; ng++) {
                uint32_t bf[4];
                int row = wn + ng * 16 + ((lane >> 4) << 3) + (lane & 7);
                int ckb = kc + 16 * ((lane >> 3) & 1);
                ldmx4(bf, smem_u32(Ks + row * 144 + ckb));
                #pragma unroll
                for (int mt = 0; mt < 2; mt++) {
                    mma16832(acc[mt][2 * ng],     af[mt], bf + 0);
                    mma16832(acc[mt][2 * ng + 1], af[mt], bf + 2);
                }
            }
        }
        #pragma unroll
        for (int mt = 0; mt < 2; mt++) {
            float w0 = ws[wm + mt * 16 + gid][h];
            float w1 = ws[wm + mt * 16 + 8 + gid][h];
            #pragma unroll
            for (int nt = 0; nt < 4; nt++) {
                score[mt][nt][0] += w0 * fmaxf(acc[mt][nt][0], 0.f);
                score[mt][nt][1] += w0 * fmaxf(acc[mt][nt][1], 0.f);
                score[mt][nt][2] += w1 * fmaxf(acc[mt][nt][2], 0.f);
                score[mt][nt][3] += w1 * fmaxf(acc[mt][nt][3], 0.f);
            }
        }
        if (++qs_ == 3) qs_ = 0;
    }

    #pragma unroll
    for (int mt = 0; mt < 2; mt++) {
        int r0 = t0 + wm + mt * 16 + gid;
        int r1 = r0 + 8;
        #pragma unroll
        for (int nt = 0; nt < 4; nt++) {
            int cs = s0 + wn + nt * 8 + 2 * tig;
            float2 v0, v1;
            v0.x = (cs     <= r0) ? score[mt][nt][0] * HAD_SCALE : NEG;
            v0.y = (cs + 1 <= r0) ? score[mt][nt][1] * HAD_SCALE : NEG;
            v1.x = (cs     <= r1) ? score[mt][nt][2] * HAD_SCALE : NEG;
            v1.y = (cs + 1 <= r1) ? score[mt][nt][3] * HAD_SCALE : NEG;
            *(float2*)&out[(size_t)r0 * S_LEN + cs] = v0;
            *(float2*)&out[(size_t)r1 * S_LEN + cs] = v1;
        }
    }
}

// ---------------------------------------------------------------------------
extern "C" void kernel_launch(void* const* d_in, const int* in_sizes, int n_in,
                              void* d_out, int out_size) {
    const float* x    = (const float*)d_in[0];
    const float* qlat = (const float*)d_in[1];
    const float* Wq   = (const float*)d_in[2];
    const float* Wk   = (const float*)d_in[3];
    const float* ln_g = (const float*)d_in[4];
    const float* ln_b = (const float*)d_in[5];
    const float* Wwt  = (const float*)d_in[6];
    float* out = (float*)d_out;

    cudaFuncSetAttribute(proj_kernel,   cudaFuncAttributeMaxDynamicSharedMemorySize, 208896);
    cudaFuncSetAttribute(scores_kernel, cudaFuncAttributeMaxDynamicSharedMemorySize, 73728);

    prep_kernel<<<PREP_BLOCKS, 256>>>(x, qlat, Wq, Wk, Wwt);

    proj_kernel<<<dim3(9, S_LEN / 128), 512, 208896>>>(ln_g, ln_b);

    w_kernel<<<S_LEN, 256>>>(x);

    scores_kernel<<<dim3(S_LEN / 128, S_LEN / 128), 512, 73728>>>(out);
}

// round 14
// speedup vs baseline: 1.3574x; 1.0202x over previous
#include <cuda_runtime.h>
#include <cuda_bf16.h>
#include <stdint.h>

#define S_LEN 4096
#define D_MODEL 2048
#define D_CQ 1536
#define H 8
#define D 128
#define NEG (-1000000000.0f)
#define HAD_SCALE 0.08838834764831845f   // 128^-0.5

// ---------------- scratch (device globals; no allocation allowed) ----------
__device__ uint8_t g_qp8[S_LEN * H * D];        // q' e4m3 [t][h][d]
__device__ uint8_t g_kp8[S_LEN * D];            // k' e4m3 [s][d]
__device__ float   g_w[S_LEN * H];              // [t][h]
__device__ uint8_t g_x8 [S_LEN * D_MODEL];      // x e4m3
__device__ uint8_t g_ql8[S_LEN * D_CQ];         // q_latent e4m3
__device__ uint8_t g_wqt8[(H * D) * D_CQ];      // Wq^T e4m3 [N=1024][K=1536]
__device__ uint8_t g_wkt8[D * D_MODEL];         // Wk^T e4m3 [N=128][K=2048]
__device__ float   g_wwtT[H * D_MODEL];         // Wwt^T [h][k]

// ---------------- asm helpers ---------------------------------------------
__device__ __forceinline__ uint32_t smem_u32(const void* p) {
    return (uint32_t)__cvta_generic_to_shared(p);
}
__device__ __forceinline__ void cp16(uint32_t dst, const void* src) {
    asm volatile("cp.async.cg.shared.global [%0], [%1], 16;\n" :: "r"(dst), "l"(src));
}
__device__ __forceinline__ void cp_commit() {
    asm volatile("cp.async.commit_group;\n" ::: "memory");
}
template<int N> __device__ __forceinline__ void cp_wait() {
    asm volatile("cp.async.wait_group %0;\n" :: "n"(N) : "memory");
}
__device__ __forceinline__ void ldmx4(uint32_t* r, uint32_t a) {
    asm volatile("ldmatrix.sync.aligned.m8n8.x4.shared.b16 {%0,%1,%2,%3}, [%4];\n"
                 : "=r"(r[0]), "=r"(r[1]), "=r"(r[2]), "=r"(r[3]) : "r"(a));
}
// fp8 e4m3 mma: D(fp32) += A(e4m3) * B(e4m3), m16n8k32
__device__ __forceinline__ void mma16832(float c[4], const uint32_t a[4], const uint32_t b[2]) {
    asm volatile(
        "mma.sync.aligned.m16n8k32.row.col.f32.e4m3.e4m3.f32 "
        "{%0,%1,%2,%3}, {%4,%5,%6,%7}, {%8,%9}, {%0,%1,%2,%3};\n"
        : "+f"(c[0]), "+f"(c[1]), "+f"(c[2]), "+f"(c[3])
        : "r"(a[0]), "r"(a[1]), "r"(a[2]), "r"(a[3]), "r"(b[0]), "r"(b[1]));
}
// pack two floats -> e4m3x2 (low byte = lo)
__device__ __forceinline__ uint32_t pk2(float lo, float hi) {
    uint16_t r;
    asm("cvt.rn.satfinite.e4m3x2.f32 %0, %1, %2;" : "=h"(r) : "f"(hi), "f"(lo));
    return (uint32_t)r;
}

// ---------------- fused prep kernel ----------------------------------------
// Segments (blockIdx.x): cvt x | cvt ql | tconv Wq | tconv Wk | wwt^T
#define N_X   (S_LEN * D_MODEL)           // 8388608
#define N_QL  (S_LEN * D_CQ)              // 6291456
#define B_CVTX (N_X / 2048)               // 4096
#define B_CVTQ (N_QL / 2048)              // 3072
#define B_TWQ  ((D_CQ / 32) * ((H * D) / 32))   // 1536
#define B_TWK  ((D_MODEL / 32) * (D / 32))      // 256
#define B_WWT  (D_MODEL / 256)                  // 8
#define PREP_BLOCKS (B_CVTX + B_CVTQ + B_TWQ + B_TWK + B_WWT)

__device__ __forceinline__ void cvt8_seg(const float* __restrict__ s,
                                         uint8_t* __restrict__ d, long j) {
    float4 v0 = *(const float4*)(s + j);
    float4 v1 = *(const float4*)(s + j + 4);
    uint2 u;
    u.x = pk2(v0.x, v0.y) | (pk2(v0.z, v0.w) << 16);
    u.y = pk2(v1.x, v1.y) | (pk2(v1.z, v1.w) << 16);
    *(uint2*)(d + j) = u;
}

__device__ __forceinline__ void tconv8_seg(const float* __restrict__ src,
                                           uint8_t* __restrict__ dst,
                                           int K, int N, int k0, int n0,
                                           float (*t)[33]) {
    const int tx = threadIdx.x & 31, ty = threadIdx.x >> 5;  // 32 x 8
    #pragma unroll
    for (int i = 0; i < 4; i++)
        t[ty + 8 * i][tx] = src[(size_t)(k0 + ty + 8 * i) * N + n0 + tx];
    __syncthreads();
    const int nr = threadIdx.x >> 3;          // 0..31 output row (n)
    const int kq = (threadIdx.x & 7) * 4;     // k quad
    uint32_t w = pk2(t[kq][nr], t[kq + 1][nr]) | (pk2(t[kq + 2][nr], t[kq + 3][nr]) << 16);
    *(uint32_t*)&dst[(size_t)(n0 + nr) * K + k0 + kq] = w;
}

__global__ __launch_bounds__(256) void prep_kernel(const float* __restrict__ x,
                                                   const float* __restrict__ ql,
                                                   const float* __restrict__ Wq,
                                                   const float* __restrict__ Wk,
                                                   const float* __restrict__ Wwt) {
    __shared__ float t[32][33];
    int b = blockIdx.x;
    if (b < B_CVTX) {
        cvt8_seg(x, g_x8, ((long)b * 256 + threadIdx.x) * 8);
        return;
    }
    b -= B_CVTX;
    if (b < B_CVTQ) {
        cvt8_seg(ql, g_ql8, ((long)b * 256 + threadIdx.x) * 8);
        return;
    }
    b -= B_CVTQ;
    if (b < B_TWQ) {
        int k0 = (b % (D_CQ / 32)) * 32;
        int n0 = (b / (D_CQ / 32)) * 32;
        tconv8_seg(Wq, g_wqt8, D_CQ, H * D, k0, n0, t);
        return;
    }
    b -= B_TWQ;
    if (b < B_TWK) {
        int k0 = (b % (D_MODEL / 32)) * 32;
        int n0 = (b / (D_MODEL / 32)) * 32;
        tconv8_seg(Wk, g_wkt8, D_MODEL, D, k0, n0, t);
        return;
    }
    b -= B_TWK;
    {
        int k = b * 256 + threadIdx.x;
        #pragma unroll
        for (int h = 0; h < H; h++)
            g_wwtT[h * D_MODEL + k] = Wwt[(size_t)k * H + h];
    }
}

// ---------------------------------------------------------------------------
// Merged projection GEMM (fp8 e4m3 mma.sync, 3-stage cp.async ring).
// grid (9, 32): blockIdx.x 0..7 -> Q head tiles, 8 -> K tile (+LayerNorm).
// 512 threads, 128x128 tile, warp tile 32x32, K chunks of 256 e4m3 (256B rows,
// 272B stride). dyn smem: 3 x (34816 + 34816) = 208896; Es[128][132] aliases.
// ---------------------------------------------------------------------------
__global__ __launch_bounds__(512, 1) void proj_kernel(const float* __restrict__ ln_g,
                                                      const float* __restrict__ ln_b) {
    extern __shared__ char sm[];
    __shared__ float s_mu[128], s_rs[128];

    const int tile = blockIdx.x;
    const bool isK = (tile == 8);
    const uint8_t* A  = isK ? g_x8   : g_ql8;    // [4096][Kdim] bytes
    const uint8_t* Bt = isK ? g_wkt8 : g_wqt8;   // [N][Kdim] bytes
    const int Kdim = isK ? D_MODEL : D_CQ;
    const int n0   = isK ? 0 : tile * 128;
    uint8_t* outp  = isK ? g_kp8 : g_qp8;
    const int Old  = isK ? D : (H * D);
    const int m0 = blockIdx.y * 128;

    const int tid = threadIdx.x, lane = tid & 31, warp = tid >> 5;
    const int wm = (warp & 3) * 32;          // 4 m-warps
    const int wn = (warp >> 2) * 32;         // 4 n-warps
    const int gid = lane >> 2, tig = lane & 3;

    const int KT = Kdim >> 8;                // chunks of 256 bytes

    auto fill = [&](int st, int k0) {
        char* as = sm + st * 69632;
        char* bs = as + 34816;
        #pragma unroll
        for (int i = 0; i < 4; i++) {
            int c = tid + i * 512;
            int r = c >> 4, g = c & 15;
            cp16(smem_u32(as + r * 272 + g * 16), A  + (size_t)(m0 + r) * Kdim + k0 + g * 16);
        }
        #pragma unroll
        for (int i = 0; i < 4; i++) {
            int c = tid + i * 512;
            int r = c >> 4, g = c & 15;
            cp16(smem_u32(bs + r * 272 + g * 16), Bt + (size_t)(n0 + r) * Kdim + k0 + g * 16);
        }
    };

    float acc[2][4][4];
    #pragma unroll
    for (int mt = 0; mt < 2; mt++)
        #pragma unroll
        for (int nt = 0; nt < 4; nt++)
            #pragma unroll
            for (int j = 0; j < 4; j++) acc[mt][nt][j] = 0.f;

    fill(0, 0);   cp_commit();
    fill(1, 256); cp_commit();

    int cs_ = 0;                   // compute slot = kt % 3
    for (int kt = 0; kt < KT; kt++) {
        cp_wait<1>();
        __syncthreads();           // slot (kt+2)%3 == (kt-1)%3 now free for refill
        if (kt + 2 < KT) {
            int fs = cs_ + 2; if (fs >= 3) fs -= 3;
            fill(fs, (kt + 2) * 256);
        }
        cp_commit();               // one group per iteration (possibly empty)

        const char* as = sm + cs_ * 69632;
        const char* bs = as + 34816;
        #pragma unroll
        for (int kc = 0; kc < 256; kc += 32) {        // 8 k32 steps
            uint32_t af[2][4];
            #pragma unroll
            for (int mt = 0; mt < 2; mt++) {
                uint32_t ad = smem_u32(as + (wm + mt * 16 + (lane & 15)) * 272
                                          + kc + 16 * (lane >> 4));
                ldmx4(af[mt], ad);
            }
            #pragma unroll
            for (int ng = 0; ng < 2; ng++) {
                uint32_t bf[4];
                int row = wn + ng * 16 + ((lane >> 4) << 3) + (lane & 7);
                int ckb = kc + 16 * ((lane >> 3) & 1);
                ldmx4(bf, smem_u32(bs + row * 272 + ckb));
                #pragma unroll
                for (int mt = 0; mt < 2; mt++) {
                    mma16832(acc[mt][2 * ng],     af[mt], bf + 0);
                    mma16832(acc[mt][2 * ng + 1], af[mt], bf + 2);
                }
            }
        }
        if (++cs_ == 3) cs_ = 0;
    }
    cp_wait<0>();
    __syncthreads();

    // ---- epilogue: acc -> Es (fp32, aliases stage buffers) ----
    float* Es = (float*)sm;    // [128][132]
    #pragma unroll
    for (int mt = 0; mt < 2; mt++) {
        int r0 = wm + mt * 16 + gid;
        int r1 = r0 + 8;
        #pragma unroll
        for (int nt = 0; nt < 4; nt++) {
            int c = wn + nt * 8 + 2 * tig;
            Es[r0 * 132 + c]     = acc[mt][nt][0];
            Es[r0 * 132 + c + 1] = acc[mt][nt][1];
            Es[r1 * 132 + c]     = acc[mt][nt][2];
            Es[r1 * 132 + c + 1] = acc[mt][nt][3];
        }
    }
    __syncthreads();

    if (isK) {
        if (tid < 128) {
            float sum = 0.f, sq = 0.f;
            #pragma unroll 4
            for (int d2 = 0; d2 < 128; d2++) {
                float v = Es[tid * 132 + d2];
                sum += v; sq += v * v;
            }
            float mu  = sum * (1.0f / 128.0f);
            float var = sq * (1.0f / 128.0f) - mu * mu;
            s_mu[tid] = mu;
            s_rs[tid] = rsqrtf(var + 1e-5f);
        }
        __syncthreads();
        for (int it = tid; it < 128 * 128; it += 512) {
            int r = it >> 7, d2 = it & 127;
            Es[r * 132 + d2] = (Es[r * 132 + d2] - s_mu[r]) * s_rs[r] * ln_g[d2] + ln_b[d2];
        }
        __syncthreads();
    }
    // RoPE: pairs (j, j+32), j<32; freq = 10000^(-j/32)
    for (int it = tid; it < 128 * 32; it += 512) {
        int r = it >> 5, j = it & 31;
        float t = (float)(m0 + r);
        float freq = exp2f((float)j * (-0.41524101186092029f));
        float sn, cs2;
        sincosf(t * freq, &sn, &cs2);
        float x1 = Es[r * 132 + j], x2 = Es[r * 132 + j + 32];
        Es[r * 132 + j]      = x1 * cs2 - x2 * sn;
        Es[r * 132 + j + 32] = x1 * sn + x2 * cs2;
    }
    // Hadamard (7 butterfly stages)
    for (int step = 1; step < 128; step <<= 1) {
        __syncthreads();
        for (int it = tid; it < 128 * 64; it += 512) {
            int r = it >> 6, pp = it & 63;
            int i = ((pp & ~(step - 1)) << 1) | (pp & (step - 1));
            float a = Es[r * 132 + i], b = Es[r * 132 + i + step];
            Es[r * 132 + i]        = a + b;
            Es[r * 132 + i + step] = a - b;
        }
    }
    __syncthreads();
    // pack fp8 output (4 bytes per thread per iter)
    for (int it = tid; it < 128 * 32; it += 512) {
        int r = it >> 5, q4 = (it & 31) * 4;
        float e0 = Es[r * 132 + q4]     * HAD_SCALE;
        float e1 = Es[r * 132 + q4 + 1] * HAD_SCALE;
        float e2 = Es[r * 132 + q4 + 2] * HAD_SCALE;
        float e3 = Es[r * 132 + q4 + 3] * HAD_SCALE;
        uint32_t wv = pk2(e0, e1) | (pk2(e2, e3) << 16);
        *(uint32_t*)&outp[(size_t)(m0 + r) * Old + n0 + q4] = wv;
    }
}

// ---------------------------------------------------------------------------
// w[t][h] = x[t] . Wwt[:,h].  fp32 x row staged via smem; Wwt^T coalesced.
// ---------------------------------------------------------------------------
__global__ __launch_bounds__(256) void w_kernel(const float* __restrict__ x) {
    __shared__ float xr[D_MODEL];   // 8 KB
    const int t = blockIdx.x;
    const int tid = threadIdx.x;
    *(float4*)&xr[tid * 8]     = *(const float4*)&x[(size_t)t * D_MODEL + tid * 8];
    *(float4*)&xr[tid * 8 + 4] = *(const float4*)&x[(size_t)t * D_MODEL + tid * 8 + 4];
    __syncthreads();
    const int warp = tid >> 5, lane = tid & 31;
    const float* wt = g_wwtT + warp * D_MODEL;
    float sum = 0.f;
    #pragma unroll 8
    for (int k = lane; k < D_MODEL; k += 32)
        sum += xr[k] * wt[k];
    #pragma unroll
    for (int o = 16; o > 0; o >>= 1) sum += __shfl_xor_sync(0xffffffffu, sum, o);
    if (lane == 0) g_w[(size_t)t * H + warp] = sum;
}

// ---------------------------------------------------------------------------
// scores: tile 128(t) x 128(s), grid (32, 32), 512 threads. fp8 e4m3 mma.
// K tile + ALL 8 Q head tiles resident in smem (9 x 18432 = 165888 B).
// ONE cp_wait + ONE sync total; head loop is pure compute (no barriers).
// ---------------------------------------------------------------------------
__global__ __launch_bounds__(512, 1) void scores_kernel(float* __restrict__ out) {
    const int s0 = blockIdx.x * 128;
    const int t0 = blockIdx.y * 128;
    const int tid = threadIdx.x;

    if (s0 > t0 + 127) {   // fully masked tile
        const float4 n4 = make_float4(NEG, NEG, NEG, NEG);
        for (int it = tid; it < 128 * 32; it += 512) {
            int r = it >> 5, c = (it & 31) * 4;
            *(float4*)&out[(size_t)(t0 + r) * S_LEN + s0 + c] = n4;
        }
        return;
    }

    extern __shared__ char sm[];
    char* Ks = sm;                          // [128][144B]
    char* Qs = sm + 18432;                  // 8 slots x [128][144B]
    __shared__ float ws[128][8];

    const int lane = tid & 31, warp = tid >> 5;
    const int wm = (warp & 3) * 32;
    const int wn = (warp >> 2) * 32;
    const int gid = lane >> 2, tig = lane & 3;

    for (int it = tid; it < 1024; it += 512)
        ws[it >> 3][it & 7] = g_w[(size_t)(t0 + (it >> 3)) * H + (it & 7)];

    // ---- load EVERYTHING up front: K tile + 8 Q head tiles ----
    #pragma unroll
    for (int i = 0; i < 2; i++) {
        int c = tid + i * 512;
        int r = c >> 3, g = c & 7;
        cp16(smem_u32(Ks + r * 144 + g * 16), g_kp8 + (size_t)(s0 + r) * D + g * 16);
    }
    #pragma unroll
    for (int h = 0; h < H; h++) {
        char* Qn = Qs + h * 18432;
        #pragma unroll
        for (int i = 0; i < 2; i++) {
            int c = tid + i * 512;
            int r = c >> 3, g = c & 7;
            cp16(smem_u32(Qn + r * 144 + g * 16),
                 g_qp8 + (size_t)(t0 + r) * (H * D) + h * D + g * 16);
        }
    }
    cp_commit();
    cp_wait<0>();
    __syncthreads();                        // the ONLY barrier

    float score[2][4][4];
    #pragma unroll
    for (int mt = 0; mt < 2; mt++)
        #pragma unroll
        for (int nt = 0; nt < 4; nt++)
            #pragma unroll
            for (int j = 0; j < 4; j++) score[mt][nt][j] = 0.f;

    for (int h = 0; h < H; h++) {
        const char* Qb = Qs + h * 18432;

        float acc[2][4][4];
        #pragma unroll
        for (int mt = 0; mt < 2; mt++)
            #pragma unroll
            for (int nt = 0; nt < 4; nt++)
                #pragma unroll
                for (int j = 0; j < 4; j++) acc[mt][nt][j] = 0.f;

        #pragma unroll
        for (int kc = 0; kc < 128; kc += 32) {        // 4 k32 steps
            uint32_t af[2][4];
            #pragma unroll
            for (int mt = 0; mt < 2; mt++) {
                uint32_t ad = smem_u32(Qb + (wm + mt * 16 + (lane & 15)) * 144
                                          + kc + 16 * (lane >> 4));
                ldmx4(af[mt], ad);
            }
            #pragma unroll
            for (int ng = 0; ng < 2; ng++) {
                uint32_t bf[4];
                int row = wn + ng * 16 + ((lane >> 4) << 3) + (lane & 7);
                int ckb = kc + 16 * ((lane >> 3) & 1);
                ldmx4(bf, smem_u32(Ks + row * 144 + ckb));
                #pragma unroll
                for (int mt = 0; mt < 2; mt++) {
                    mma16832(acc[mt][2 * ng],     af[mt], bf + 0);
                    mma16832(acc[mt][2 * ng + 1], af[mt], bf + 2);
                }
            }
        }
        #pragma unroll
        for (int mt = 0; mt < 2; mt++) {
            float w0 = ws[wm + mt * 16 + gid][h];
            float w1 = ws[wm + mt * 16 + 8 + gid][h];
            #pragma unroll
            for (int nt = 0; nt < 4; nt++) {
                score[mt][nt][0] += w0 * fmaxf(acc[mt][nt][0], 0.f);
                score[mt][nt][1] += w0 * fmaxf(acc[mt][nt][1], 0.f);
                score[mt][nt][2] += w1 * fmaxf(acc[mt][nt][2], 0.f);
                score[mt][nt][3] += w1 * fmaxf(acc[mt][nt][3], 0.f);
            }
        }
    }

    #pragma unroll
    for (int mt = 0; mt < 2; mt++) {
        int r0 = t0 + wm + mt * 16 + gid;
        int r1 = r0 + 8;
        #pragma unroll
        for (int nt = 0; nt < 4; nt++) {
            int cs = s0 + wn + nt * 8 + 2 * tig;
            float2 v0, v1;
            v0.x = (cs     <= r0) ? score[mt][nt][0] * HAD_SCALE : NEG;
            v0.y = (cs + 1 <= r0) ? score[mt][nt][1] * HAD_SCALE : NEG;
            v1.x = (cs     <= r1) ? score[mt][nt][2] * HAD_SCALE : NEG;
            v1.y = (cs + 1 <= r1) ? score[mt][nt][3] * HAD_SCALE : NEG;
            *(float2*)&out[(size_t)r0 * S_LEN + cs] = v0;
            *(float2*)&out[(size_t)r1 * S_LEN + cs] = v1;
        }
    }
}

// ---------------------------------------------------------------------------
extern "C" void kernel_launch(void* const* d_in, const int* in_sizes, int n_in,
                              void* d_out, int out_size) {
    const float* x    = (const float*)d_in[0];
    const float* qlat = (const float*)d_in[1];
    const float* Wq   = (const float*)d_in[2];
    const float* Wk   = (const float*)d_in[3];
    const float* ln_g = (const float*)d_in[4];
    const float* ln_b = (const float*)d_in[5];
    const float* Wwt  = (const float*)d_in[6];
    float* out = (float*)d_out;

    cudaFuncSetAttribute(proj_kernel,   cudaFuncAttributeMaxDynamicSharedMemorySize, 208896);
    cudaFuncSetAttribute(scores_kernel, cudaFuncAttributeMaxDynamicSharedMemorySize, 165888);

    prep_kernel<<<PREP_BLOCKS, 256>>>(x, qlat, Wq, Wk, Wwt);

    proj_kernel<<<dim3(9, S_LEN / 128), 512, 208896>>>(ln_g, ln_b);

    w_kernel<<<S_LEN, 256>>>(x);

    scores_kernel<<<dim3(S_LEN / 128, S_LEN / 128), 512, 165888>>>(out);
}

// round 17
// speedup vs baseline: 1.4005x; 1.0317x over previous
#include <cuda_runtime.h>
#include <cuda_bf16.h>
#include <cuda_fp16.h>
#include <stdint.h>

#define S_LEN 4096
#define D_MODEL 2048
#define D_CQ 1536
#define H 8
#define D 128
#define NEG (-1000000000.0f)
#define HAD_SCALE 0.08838834764831845f   // 128^-0.5

// ---------------- scratch (device globals; no allocation allowed) ----------
__device__ uint8_t g_qp8[S_LEN * H * D];        // q' e4m3 [t][h][d]
__device__ uint8_t g_kp8[S_LEN * D];            // k' e4m3 [s][d]
__device__ float   g_w[S_LEN * H];              // [t][h]
__device__ uint8_t g_x8 [S_LEN * D_MODEL];      // x e4m3
__device__ uint8_t g_ql8[S_LEN * D_CQ];         // q_latent e4m3
__device__ uint8_t g_wqt8[(H * D) * D_CQ];      // Wq^T e4m3 [N=1024][K=1536]
__device__ uint8_t g_wkt8[D * D_MODEL];         // Wk^T e4m3 [N=128][K=2048]
__device__ float   g_wwtT[H * D_MODEL];         // Wwt^T [h][k]

// ---------------- asm helpers ---------------------------------------------
__device__ __forceinline__ uint32_t smem_u32(const void* p) {
    return (uint32_t)__cvta_generic_to_shared(p);
}
__device__ __forceinline__ void cp16(uint32_t dst, const void* src) {
    asm volatile("cp.async.cg.shared.global [%0], [%1], 16;\n" :: "r"(dst), "l"(src));
}
__device__ __forceinline__ void cp_commit() {
    asm volatile("cp.async.commit_group;\n" ::: "memory");
}
template<int N> __device__ __forceinline__ void cp_wait() {
    asm volatile("cp.async.wait_group %0;\n" :: "n"(N) : "memory");
}
__device__ __forceinline__ void ldmx4(uint32_t* r, uint32_t a) {
    asm volatile("ldmatrix.sync.aligned.m8n8.x4.shared.b16 {%0,%1,%2,%3}, [%4];\n"
                 : "=r"(r[0]), "=r"(r[1]), "=r"(r[2]), "=r"(r[3]) : "r"(a));
}
// fp8 e4m3 mma, fp32 acc (used in proj)
__device__ __forceinline__ void mma16832(float c[4], const uint32_t a[4], const uint32_t b[2]) {
    asm volatile(
        "mma.sync.aligned.m16n8k32.row.col.f32.e4m3.e4m3.f32 "
        "{%0,%1,%2,%3}, {%4,%5,%6,%7}, {%8,%9}, {%0,%1,%2,%3};\n"
        : "+f"(c[0]), "+f"(c[1]), "+f"(c[2]), "+f"(c[3])
        : "r"(a[0]), "r"(a[1]), "r"(a[2]), "r"(a[3]), "r"(b[0]), "r"(b[1]));
}
// fp8 e4m3 mma, fp16 acc (used in scores): D = 2 x half2 regs
__device__ __forceinline__ void mma16832h(uint32_t c[2], const uint32_t a[4], const uint32_t b[2]) {
    asm volatile(
        "mma.sync.aligned.m16n8k32.row.col.f16.e4m3.e4m3.f16 "
        "{%0,%1}, {%2,%3,%4,%5}, {%6,%7}, {%0,%1};\n"
        : "+r"(c[0]), "+r"(c[1])
        : "r"(a[0]), "r"(a[1]), "r"(a[2]), "r"(a[3]), "r"(b[0]), "r"(b[1]));
}
// pack two floats -> e4m3x2 (low byte = lo)
__device__ __forceinline__ uint32_t pk2(float lo, float hi) {
    uint16_t r;
    asm("cvt.rn.satfinite.e4m3x2.f32 %0, %1, %2;" : "=h"(r) : "f"(hi), "f"(lo));
    return (uint32_t)r;
}

// ---------------- fused prep kernel ----------------------------------------
#define N_X   (S_LEN * D_MODEL)           // 8388608
#define N_QL  (S_LEN * D_CQ)              // 6291456
#define B_CVTX (N_X / 2048)               // 4096
#define B_CVTQ (N_QL / 2048)              // 3072
#define B_TWQ  ((D_CQ / 32) * ((H * D) / 32))   // 1536
#define B_TWK  ((D_MODEL / 32) * (D / 32))      // 256
#define B_WWT  (D_MODEL / 256)                  // 8
#define PREP_BLOCKS (B_CVTX + B_CVTQ + B_TWQ + B_TWK + B_WWT)

__device__ __forceinline__ void cvt8_seg(const float* __restrict__ s,
                                         uint8_t* __restrict__ d, long j) {
    float4 v0 = *(const float4*)(s + j);
    float4 v1 = *(const float4*)(s + j + 4);
    uint2 u;
    u.x = pk2(v0.x, v0.y) | (pk2(v0.z, v0.w) << 16);
    u.y = pk2(v1.x, v1.y) | (pk2(v1.z, v1.w) << 16);
    *(uint2*)(d + j) = u;
}

__device__ __forceinline__ void tconv8_seg(const float* __restrict__ src,
                                           uint8_t* __restrict__ dst,
                                           int K, int N, int k0, int n0,
                                           float (*t)[33]) {
    const int tx = threadIdx.x & 31, ty = threadIdx.x >> 5;  // 32 x 8
    #pragma unroll
    for (int i = 0; i < 4; i++)
        t[ty + 8 * i][tx] = src[(size_t)(k0 + ty + 8 * i) * N + n0 + tx];
    __syncthreads();
    const int nr = threadIdx.x >> 3;          // 0..31 output row (n)
    const int kq = (threadIdx.x & 7) * 4;     // k quad
    uint32_t w = pk2(t[kq][nr], t[kq + 1][nr]) | (pk2(t[kq + 2][nr], t[kq + 3][nr]) << 16);
    *(uint32_t*)&dst[(size_t)(n0 + nr) * K + k0 + kq] = w;
}

__global__ __launch_bounds__(256) void prep_kernel(const float* __restrict__ x,
                                                   const float* __restrict__ ql,
                                                   const float* __restrict__ Wq,
                                                   const float* __restrict__ Wk,
                                                   const float* __restrict__ Wwt) {
    __shared__ float t[32][33];
    int b = blockIdx.x;
    if (b < B_CVTX) {
        cvt8_seg(x, g_x8, ((long)b * 256 + threadIdx.x) * 8);
        return;
    }
    b -= B_CVTX;
    if (b < B_CVTQ) {
        cvt8_seg(ql, g_ql8, ((long)b * 256 + threadIdx.x) * 8);
        return;
    }
    b -= B_CVTQ;
    if (b < B_TWQ) {
        int k0 = (b % (D_CQ / 32)) * 32;
        int n0 = (b / (D_CQ / 32)) * 32;
        tconv8_seg(Wq, g_wqt8, D_CQ, H * D, k0, n0, t);
        return;
    }
    b -= B_TWQ;
    if (b < B_TWK) {
        int k0 = (b % (D_MODEL / 32)) * 32;
        int n0 = (b / (D_MODEL / 32)) * 32;
        tconv8_seg(Wk, g_wkt8, D_MODEL, D, k0, n0, t);
        return;
    }
    b -= B_TWK;
    {
        int k = b * 256 + threadIdx.x;
        #pragma unroll
        for (int h = 0; h < H; h++)
            g_wwtT[h * D_MODEL + k] = Wwt[(size_t)k * H + h];
    }
}

// ---------------------------------------------------------------------------
// Merged projection GEMM (fp8 e4m3 mma.sync, 3-stage cp.async ring).
// grid (9, 32): blockIdx.x 0..7 -> Q head tiles, 8 -> K tile (+LayerNorm).
// ---------------------------------------------------------------------------
__global__ __launch_bounds__(512, 1) void proj_kernel(const float* __restrict__ ln_g,
                                                      const float* __restrict__ ln_b) {
    extern __shared__ char sm[];
    __shared__ float s_mu[128], s_rs[128];

    const int tile = blockIdx.x;
    const bool isK = (tile == 8);
    const uint8_t* A  = isK ? g_x8   : g_ql8;    // [4096][Kdim] bytes
    const uint8_t* Bt = isK ? g_wkt8 : g_wqt8;   // [N][Kdim] bytes
    const int Kdim = isK ? D_MODEL : D_CQ;
    const int n0   = isK ? 0 : tile * 128;
    uint8_t* outp  = isK ? g_kp8 : g_qp8;
    const int Old  = isK ? D : (H * D);
    const int m0 = blockIdx.y * 128;

    const int tid = threadIdx.x, lane = tid & 31, warp = tid >> 5;
    const int wm = (warp & 3) * 32;          // 4 m-warps
    const int wn = (warp >> 2) * 32;         // 4 n-warps
    const int gid = lane >> 2, tig = lane & 3;

    const int KT = Kdim >> 8;                // chunks of 256 bytes

    auto fill = [&](int st, int k0) {
        char* as = sm + st * 69632;
        char* bs = as + 34816;
        #pragma unroll
        for (int i = 0; i < 4; i++) {
            int c = tid + i * 512;
            int r = c >> 4, g = c & 15;
            cp16(smem_u32(as + r * 272 + g * 16), A  + (size_t)(m0 + r) * Kdim + k0 + g * 16);
        }
        #pragma unroll
        for (int i = 0; i < 4; i++) {
            int c = tid + i * 512;
            int r = c >> 4, g = c & 15;
            cp16(smem_u32(bs + r * 272 + g * 16), Bt + (size_t)(n0 + r) * Kdim + k0 + g * 16);
        }
    };

    float acc[2][4][4];
    #pragma unroll
    for (int mt = 0; mt < 2; mt++)
        #pragma unroll
        for (int nt = 0; nt < 4; nt++)
            #pragma unroll
            for (int j = 0; j < 4; j++) acc[mt][nt][j] = 0.f;

    fill(0, 0);   cp_commit();
    fill(1, 256); cp_commit();

    int cs_ = 0;                   // compute slot = kt % 3
    for (int kt = 0; kt < KT; kt++) {
        cp_wait<1>();
        __syncthreads();           // slot (kt+2)%3 == (kt-1)%3 now free for refill
        if (kt + 2 < KT) {
            int fs = cs_ + 2; if (fs >= 3) fs -= 3;
            fill(fs, (kt + 2) * 256);
        }
        cp_commit();               // one group per iteration (possibly empty)

        const char* as = sm + cs_ * 69632;
        const char* bs = as + 34816;
        #pragma unroll
        for (int kc = 0; kc < 256; kc += 32) {        // 8 k32 steps
            uint32_t af[2][4];
            #pragma unroll
            for (int mt = 0; mt < 2; mt++) {
                uint32_t ad = smem_u32(as + (wm + mt * 16 + (lane & 15)) * 272
                                          + kc + 16 * (lane >> 4));
                ldmx4(af[mt], ad);
            }
            #pragma unroll
            for (int ng = 0; ng < 2; ng++) {
                uint32_t bf[4];
                int row = wn + ng * 16 + ((lane >> 4) << 3) + (lane & 7);
                int ckb = kc + 16 * ((lane >> 3) & 1);
                ldmx4(bf, smem_u32(bs + row * 272 + ckb));
                #pragma unroll
                for (int mt = 0; mt < 2; mt++) {
                    mma16832(acc[mt][2 * ng],     af[mt], bf + 0);
                    mma16832(acc[mt][2 * ng + 1], af[mt], bf + 2);
                }
            }
        }
        if (++cs_ == 3) cs_ = 0;
    }
    cp_wait<0>();
    __syncthreads();

    // ---- epilogue: acc -> Es (fp32, aliases stage buffers) ----
    float* Es = (float*)sm;    // [128][132]
    #pragma unroll
    for (int mt = 0; mt < 2; mt++) {
        int r0 = wm + mt * 16 + gid;
        int r1 = r0 + 8;
        #pragma unroll
        for (int nt = 0; nt < 4; nt++) {
            int c = wn + nt * 8 + 2 * tig;
            Es[r0 * 132 + c]     = acc[mt][nt][0];
            Es[r0 * 132 + c + 1] = acc[mt][nt][1];
            Es[r1 * 132 + c]     = acc[mt][nt][2];
            Es[r1 * 132 + c + 1] = acc[mt][nt][3];
        }
    }
    __syncthreads();

    if (isK) {
        if (tid < 128) {
            float sum = 0.f, sq = 0.f;
            #pragma unroll 4
            for (int d2 = 0; d2 < 128; d2++) {
                float v = Es[tid * 132 + d2];
                sum += v; sq += v * v;
            }
            float mu  = sum * (1.0f / 128.0f);
            float var = sq * (1.0f / 128.0f) - mu * mu;
            s_mu[tid] = mu;
            s_rs[tid] = rsqrtf(var + 1e-5f);
        }
        __syncthreads();
        for (int it = tid; it < 128 * 128; it += 512) {
            int r = it >> 7, d2 = it & 127;
            Es[r * 132 + d2] = (Es[r * 132 + d2] - s_mu[r]) * s_rs[r] * ln_g[d2] + ln_b[d2];
        }
        __syncthreads();
    }
    // RoPE: pairs (j, j+32), j<32; freq = 10000^(-j/32)
    for (int it = tid; it < 128 * 32; it += 512) {
        int r = it >> 5, j = it & 31;
        float t = (float)(m0 + r);
        float freq = exp2f((float)j * (-0.41524101186092029f));
        float sn, cs2;
        sincosf(t * freq, &sn, &cs2);
        float x1 = Es[r * 132 + j], x2 = Es[r * 132 + j + 32];
        Es[r * 132 + j]      = x1 * cs2 - x2 * sn;
        Es[r * 132 + j + 32] = x1 * sn + x2 * cs2;
    }
    // Hadamard (7 butterfly stages)
    for (int step = 1; step < 128; step <<= 1) {
        __syncthreads();
        for (int it = tid; it < 128 * 64; it += 512) {
            int r = it >> 6, pp = it & 63;
            int i = ((pp & ~(step - 1)) << 1) | (pp & (step - 1));
            float a = Es[r * 132 + i], b = Es[r * 132 + i + step];
            Es[r * 132 + i]        = a + b;
            Es[r * 132 + i + step] = a - b;
        }
    }
    __syncthreads();
    // pack fp8 output (4 bytes per thread per iter)
    for (int it = tid; it < 128 * 32; it += 512) {
        int r = it >> 5, q4 = (it & 31) * 4;
        float e0 = Es[r * 132 + q4]     * HAD_SCALE;
        float e1 = Es[r * 132 + q4 + 1] * HAD_SCALE;
        float e2 = Es[r * 132 + q4 + 2] * HAD_SCALE;
        float e3 = Es[r * 132 + q4 + 3] * HAD_SCALE;
        uint32_t wv = pk2(e0, e1) | (pk2(e2, e3) << 16);
        *(uint32_t*)&outp[(size_t)(m0 + r) * Old + n0 + q4] = wv;
    }
}

// ---------------------------------------------------------------------------
// w[t][h] = x[t] . Wwt[:,h].  fp32 x row staged via smem; Wwt^T coalesced.
// ---------------------------------------------------------------------------
__global__ __launch_bounds__(256) void w_kernel(const float* __restrict__ x) {
    __shared__ float xr[D_MODEL];   // 8 KB
    const int t = blockIdx.x;
    const int tid = threadIdx.x;
    *(float4*)&xr[tid * 8]     = *(const float4*)&x[(size_t)t * D_MODEL + tid * 8];
    *(float4*)&xr[tid * 8 + 4] = *(const float4*)&x[(size_t)t * D_MODEL + tid * 8 + 4];
    __syncthreads();
    const int warp = tid >> 5, lane = tid & 31;
    const float* wt = g_wwtT + warp * D_MODEL;
    float sum = 0.f;
    #pragma unroll 8
    for (int k = lane; k < D_MODEL; k += 32)
        sum += xr[k] * wt[k];
    #pragma unroll
    for (int o = 16; o > 0; o >>= 1) sum += __shfl_xor_sync(0xffffffffu, sum, o);
    if (lane == 0) g_w[(size_t)t * H + warp] = sum;
}

// ---------------------------------------------------------------------------
// scores: tile 128(t) x 128(s), grid (32, 32), 512 threads.
// fp8 e4m3 mma with FP16 accumulator -> packed half2 relu/weight epilogue
// (8 HMAX2 + 8 HFMA2 per head instead of 16 FMNMX + 16 FFMA).
// K tile + ALL 8 Q head tiles resident in smem (9 x 18432 = 165888 B).
// ONE cp_wait + ONE sync total; head loop is pure compute.
// ---------------------------------------------------------------------------
__global__ __launch_bounds__(512, 1) void scores_kernel(float* __restrict__ out) {
    const int s0 = blockIdx.x * 128;
    const int t0 = blockIdx.y * 128;
    const int tid = threadIdx.x;

    if (s0 > t0 + 127) {   // fully masked tile
        const float4 n4 = make_float4(NEG, NEG, NEG, NEG);
        for (int it = tid; it < 128 * 32; it += 512) {
            int r = it >> 5, c = (it & 31) * 4;
            *(float4*)&out[(size_t)(t0 + r) * S_LEN + s0 + c] = n4;
        }
        return;
    }

    extern __shared__ char sm[];
    char* Ks = sm;                          // [128][144B]
    char* Qs = sm + 18432;                  // 8 slots x [128][144B]
    __shared__ float ws[128][8];

    const int lane = tid & 31, warp = tid >> 5;
    const int wm = (warp & 3) * 32;
    const int wn = (warp >> 2) * 32;
    const int gid = lane >> 2, tig = lane & 3;

    for (int it = tid; it < 1024; it += 512)
        ws[it >> 3][it & 7] = g_w[(size_t)(t0 + (it >> 3)) * H + (it & 7)];

    // ---- load EVERYTHING up front: K tile + 8 Q head tiles ----
    #pragma unroll
    for (int i = 0; i < 2; i++) {
        int c = tid + i * 512;
        int r = c >> 3, g = c & 7;
        cp16(smem_u32(Ks + r * 144 + g * 16), g_kp8 + (size_t)(s0 + r) * D + g * 16);
    }
    #pragma unroll
    for (int h = 0; h < H; h++) {
        char* Qn = Qs + h * 18432;
        #pragma unroll
        for (int i = 0; i < 2; i++) {
            int c = tid + i * 512;
            int r = c >> 3, g = c & 7;
            cp16(smem_u32(Qn + r * 144 + g * 16),
                 g_qp8 + (size_t)(t0 + r) * (H * D) + h * D + g * 16);
        }
    }
    cp_commit();
    cp_wait<0>();
    __syncthreads();                        // the ONLY barrier

    const __half2 h2zero = __float2half2_rn(0.f);
    __half2 score2[2][4][2];
    #pragma unroll
    for (int mt = 0; mt < 2; mt++)
        #pragma unroll
        for (int nt = 0; nt < 4; nt++) {
            score2[mt][nt][0] = h2zero;
            score2[mt][nt][1] = h2zero;
        }

    for (int h = 0; h < H; h++) {
        const char* Qb = Qs + h * 18432;

        uint32_t acch[2][4][2];
        #pragma unroll
        for (int mt = 0; mt < 2; mt++)
            #pragma unroll
            for (int nt = 0; nt < 4; nt++) {
                acch[mt][nt][0] = 0u;
                acch[mt][nt][1] = 0u;
            }

        #pragma unroll
        for (int kc = 0; kc < 128; kc += 32) {        // 4 k32 steps
            uint32_t af[2][4];
            #pragma unroll
            for (int mt = 0; mt < 2; mt++) {
                uint32_t ad = smem_u32(Qb + (wm + mt * 16 + (lane & 15)) * 144
                                          + kc + 16 * (lane >> 4));
                ldmx4(af[mt], ad);
            }
            #pragma unroll
            for (int ng = 0; ng < 2; ng++) {
                uint32_t bf[4];
                int row = wn + ng * 16 + ((lane >> 4) << 3) + (lane & 7);
                int ckb = kc + 16 * ((lane >> 3) & 1);
                ldmx4(bf, smem_u32(Ks + row * 144 + ckb));
                #pragma unroll
                for (int mt = 0; mt < 2; mt++) {
                    mma16832h(acch[mt][2 * ng],     af[mt], bf + 0);
                    mma16832h(acch[mt][2 * ng + 1], af[mt], bf + 2);
                }
            }
        }
        #pragma unroll
        for (int mt = 0; mt < 2; mt++) {
            __half2 w0h = __float2half2_rn(ws[wm + mt * 16 + gid][h]);
            __half2 w1h = __float2half2_rn(ws[wm + mt * 16 + 8 + gid][h]);
            #pragma unroll
            for (int nt = 0; nt < 4; nt++) {
                __half2 a0 = *(__half2*)&acch[mt][nt][0];   // rows gid,  cols 2tig..
                __half2 a1 = *(__half2*)&acch[mt][nt][1];   // rows gid+8
                score2[mt][nt][0] = __hfma2(w0h, __hmax2(a0, h2zero), score2[mt][nt][0]);
                score2[mt][nt][1] = __hfma2(w1h, __hmax2(a1, h2zero), score2[mt][nt][1]);
            }
        }
    }

    #pragma unroll
    for (int mt = 0; mt < 2; mt++) {
        int r0 = t0 + wm + mt * 16 + gid;
        int r1 = r0 + 8;
        #pragma unroll
        for (int nt = 0; nt < 4; nt++) {
            int cs = s0 + wn + nt * 8 + 2 * tig;
            float2 lo = __half22float2(score2[mt][nt][0]);
            float2 hi = __half22float2(score2[mt][nt][1]);
            float2 v0, v1;
            v0.x = (cs     <= r0) ? lo.x * HAD_SCALE : NEG;
            v0.y = (cs + 1 <= r0) ? lo.y * HAD_SCALE : NEG;
            v1.x = (cs     <= r1) ? hi.x * HAD_SCALE : NEG;
            v1.y = (cs + 1 <= r1) ? hi.y * HAD_SCALE : NEG;
            *(float2*)&out[(size_t)r0 * S_LEN + cs] = v0;
            *(float2*)&out[(size_t)r1 * S_LEN + cs] = v1;
        }
    }
}

// ---------------------------------------------------------------------------
extern "C" void kernel_launch(void* const* d_in, const int* in_sizes, int n_in,
                              void* d_out, int out_size) {
    const float* x    = (const float*)d_in[0];
    const float* qlat = (const float*)d_in[1];
    const float* Wq   = (const float*)d_in[2];
    const float* Wk   = (const float*)d_in[3];
    const float* ln_g = (const float*)d_in[4];
    const float* ln_b = (const float*)d_in[5];
    const float* Wwt  = (const float*)d_in[6];
    float* out = (float*)d_out;

    cudaFuncSetAttribute(proj_kernel,   cudaFuncAttributeMaxDynamicSharedMemorySize, 208896);
    cudaFuncSetAttribute(scores_kernel, cudaFuncAttributeMaxDynamicSharedMemorySize, 165888);

    prep_kernel<<<PREP_BLOCKS, 256>>>(x, qlat, Wq, Wk, Wwt);

    w_kernel<<<S_LEN, 256>>>(x);     // independent of proj; overlaps its ramp

    proj_kernel<<<dim3(9, S_LEN / 128), 512, 208896>>>(ln_g, ln_b);

    scores_kernel<<<dim3(S_LEN / 128, S_LEN / 128), 512, 165888>>>(out);
}